// round 13
// baseline (speedup 1.0000x reference)
#include <cuda_runtime.h>
#include <cuda_bf16.h>
#include <math.h>
#include <stddef.h>

#define NEGF (-1.0e9f)
#define CLIPV 4.135166556742356f

__device__ __forceinline__ unsigned skey(float s){
    unsigned u = __float_as_uint(s);
    return (u & 0x80000000u) ? ~u : (u | 0x80000000u);
}

struct __align__(256) Scratch {
    float scores[2][279280];
    float deltas[2][1117120];
    unsigned histL[10][65536];
    int tiebufL[10][4096];
    int tiecntL[10];
    int selcntL[10];
    unsigned long long sbufL[10][1024];
    float pbL[10][4000];
    float psL[10][1000];
    float catb[2][19280];
    float cats[2][4820];
    float rois[2][4000];
    float clsl[182000];
    float boxl[728000];
    float dns[2][9000];
    float dnb[2][36000];
    float clsbPad[128];
    float boxbPad[384];
    __nv_bfloat16 hb[47663616];
    __nv_bfloat16 featsbf[47663616];
    __nv_bfloat16 cwT[256*2304];
    __nv_bfloat16 fc1wT[1024*12544];
    __nv_bfloat16 fc2wT[1024*1024];
    __nv_bfloat16 clswT[128*1024];
    __nv_bfloat16 boxwT[384*1024];
    __nv_bfloat16 roifeatb[25088000];
    __nv_bfloat16 h1b[2048000];
    __nv_bfloat16 h2b[2048000];
};
__device__ Scratch g;

__constant__ int cH[5]={208,104,52,26,13};
__constant__ int cW[5]={336,168,84,42,21};
__constant__ float cStrideF[5]={4.f,8.f,16.f,32.f,64.f};
__constant__ int cNl5[5]={209664,52416,13104,3276,819};
__constant__ int cK5[5]={1000,1000,1000,1000,819};
__constant__ int cSOff[5]={0,209664,262080,275184,278460};
__constant__ int cHOff[5]={0,139776,174720,183456,185640};
__constant__ int cOffCat[5]={0,1000,2000,3000,4000};

// ---- convert feats fp32 NHWC -> bf16 (per level) --------------------------
__global__ void cvt_feats(const float* f0,const float* f1,const float* f2,
                          const float* f3,const float* f4){
    int lvl=blockIdx.y;
    const float* src=(lvl==0)?f0:(lvl==1)?f1:(lvl==2)?f2:(lvl==3)?f3:f4;
    int Etot=2*cH[lvl]*cW[lvl]*256;
    int base=(blockIdx.x*256+threadIdx.x)*8;
    if(base>=Etot) return;
    float4 a=*(const float4*)(src+base);
    float4 b=*(const float4*)(src+base+4);
    __nv_bfloat162 r0=__floats2bfloat162_rn(a.x,a.y);
    __nv_bfloat162 r1=__floats2bfloat162_rn(a.z,a.w);
    __nv_bfloat162 r2=__floats2bfloat162_rn(b.x,b.y);
    __nv_bfloat162 r3=__floats2bfloat162_rn(b.z,b.w);
    uint4 o=make_uint4(*(unsigned*)&r0,*(unsigned*)&r1,*(unsigned*)&r2,*(unsigned*)&r3);
    *(uint4*)(g.featsbf+(size_t)cHOff[lvl]*256+base)=o;
}

// ---- transpose + convert weights: src[K][N] fp32 -> dst[Npad][K] bf16 -----
__global__ void twcvt(const float* __restrict__ src,__nv_bfloat16* __restrict__ dst,
                      int K,int N,int Npad){
    __shared__ float t[32][33];
    int kb=blockIdx.x*32, nb=blockIdx.y*32;
    int tx=threadIdx.x, ty=threadIdx.y;
#pragma unroll
    for(int d=0;d<4;d++){
        int k=kb+ty+d*8, n=nb+tx;
        t[ty+d*8][tx]=(k<K&&n<N)?src[(size_t)k*N+n]:0.f;
    }
    __syncthreads();
#pragma unroll
    for(int d=0;d<4;d++){
        int n=nb+ty+d*8, k=kb+tx;
        if(n<Npad&&k<K) dst[(size_t)n*K+k]=__float2bfloat16_rn(t[tx][ty+d*8]);
    }
}

__global__ void padbias(const float* clsb,const float* boxb){
    int i=threadIdx.x;
    if(i<128) g.clsbPad[i]=(i<91)?clsb[i]:0.f;
    if(i<384) g.boxbPad[i]=(i<364)?boxb[i]:0.f;
}

#define BPADW 20

// ========== BIG bf16 GEMM: block 256x128, 8 warps, warp tile 64x64 ========
// MODE 0: dense A[M][K]. MODE 2: fused all-level 3x3 conv over concat M.
// B: bf16 [Npad][K]. Requires K%32==0, N%128==0. Dynamic smem 60KB.
template<int MODE,bool OUTBF,bool RELU>
__global__ void __launch_bounds__(256,1)
gemm_big(const __nv_bfloat16* __restrict__ A,const __nv_bfloat16* __restrict__ Bw,
         const float* __restrict__ bias,void* __restrict__ Cout,
         int M,int N,int K){
    extern __shared__ unsigned smu[];
    unsigned* Ah=smu;                 // [2][256*BPADW]
    unsigned* Bh=smu+2*256*BPADW;     // [2][128*BPADW]
    int tid=threadIdx.x;
    int bm=blockIdx.y*256, bn=blockIdx.x*128;
    int wid=tid>>5, lane=tid&31;
    int wm=wid&3, wn=wid>>2;
    int lr=lane>>2, lc=lane&3;

    float acc[4][8][4];
#pragma unroll
    for(int i=0;i<4;i++)
#pragma unroll
        for(int j=0;j<8;j++)
#pragma unroll
            for(int q=0;q<4;q++) acc[i][j][q]=0.f;

    int m=bm+tid;                    // A loader: one row per thread
    int ay=0,ax=0,Hl=0,Wl=0; size_t base0=0;
    if(MODE==2){
        int mm=(m<M)?m:0;
        int lvl=(mm>=cHOff[1])+(mm>=cHOff[2])+(mm>=cHOff[3])+(mm>=cHOff[4]);
        Hl=cH[lvl]; Wl=cW[lvl];
        int HW=Hl*Wl;
        int rel=mm-cHOff[lvl];
        int ab=rel/HW; int rem2=rel-ab*HW;
        ay=rem2/Wl; ax=rem2-ay*Wl;
        base0=(size_t)cHOff[lvl]+(size_t)ab*HW;
    }
    int bcol=tid>>1, bhalf=tid&1;    // B loader

    uint4 aV[4]; uint4 bV0,bV1;
    auto loadG=[&](int k0){
#pragma unroll
        for(int c=0;c<4;c++) aV[c]=make_uint4(0,0,0,0);
        if(m<M){
            if(MODE==0){
                const __nv_bfloat16* p=A+(size_t)m*K+k0;
#pragma unroll
                for(int c=0;c<4;c++) aV[c]=*(const uint4*)(p+c*8);
            }else{
                int r=k0>>8;
                int ky=r/3, kx=r-ky*3;
                int yy=ay+ky-1, xx=ax+kx-1;
                if(yy>=0&&yy<Hl&&xx>=0&&xx<Wl){
                    const __nv_bfloat16* p=A+(base0+(size_t)yy*Wl+xx)*256+(k0&255);
#pragma unroll
                    for(int c=0;c<4;c++) aV[c]=*(const uint4*)(p+c*8);
                }
            }
        }
        const __nv_bfloat16* q=Bw+(size_t)(bn+bcol)*K+k0+bhalf*16;
        bV0=*(const uint4*)q; bV1=*(const uint4*)(q+8);
    };
    auto storeS=[&](int stg){
        unsigned* Ad=Ah+stg*256*BPADW+tid*BPADW;
#pragma unroll
        for(int c=0;c<4;c++) *(uint4*)(Ad+c*4)=aV[c];
        unsigned* Bd=Bh+stg*128*BPADW+bcol*BPADW+bhalf*8;
        *(uint4*)Bd=bV0; *(uint4*)(Bd+4)=bV1;
    };

    int T=K>>5;
    loadG(0); storeS(0);
    __syncthreads();
    for(int t=0;t<T;t++){
        int cur=t&1, nxt=cur^1;
        if(t+1<T) loadG((t+1)*32);
        const unsigned* Ac=Ah+cur*256*BPADW;
        const unsigned* Bc=Bh+cur*128*BPADW;
#pragma unroll
        for(int ks=0;ks<2;ks++){
            int kb=ks*8;
            unsigned af[4][4];
#pragma unroll
            for(int mt=0;mt<4;mt++){
                int r0=wm*64+mt*16+lr;
                af[mt][0]=Ac[r0*BPADW+kb+lc];
                af[mt][1]=Ac[(r0+8)*BPADW+kb+lc];
                af[mt][2]=Ac[r0*BPADW+kb+lc+4];
                af[mt][3]=Ac[(r0+8)*BPADW+kb+lc+4];
            }
#pragma unroll
            for(int nt=0;nt<8;nt++){
                int cb=wn*64+nt*8+lr;
                unsigned b0=Bc[cb*BPADW+kb+lc];
                unsigned b1=Bc[cb*BPADW+kb+lc+4];
#pragma unroll
                for(int mt=0;mt<4;mt++){
                    asm volatile(
                      "mma.sync.aligned.m16n8k16.row.col.f32.bf16.bf16.f32 "
                      "{%0,%1,%2,%3}, {%4,%5,%6,%7}, {%8,%9}, {%0,%1,%2,%3};\n"
                      : "+f"(acc[mt][nt][0]),"+f"(acc[mt][nt][1]),
                        "+f"(acc[mt][nt][2]),"+f"(acc[mt][nt][3])
                      : "r"(af[mt][0]),"r"(af[mt][1]),"r"(af[mt][2]),"r"(af[mt][3]),
                        "r"(b0),"r"(b1));
                }
            }
        }
        if(t+1<T) storeS(nxt);
        __syncthreads();
    }
#pragma unroll
    for(int mt=0;mt<4;mt++){
#pragma unroll
        for(int nt=0;nt<8;nt++){
            int r0=bm+wm*64+mt*16+lr;
            int c0=bn+wn*64+nt*8+lc*2;
            float b0=bias[c0], b1=bias[c0+1];
            float v0=acc[mt][nt][0]+b0, v1=acc[mt][nt][1]+b1;
            float v2=acc[mt][nt][2]+b0, v3=acc[mt][nt][3]+b1;
            if(RELU){ v0=fmaxf(v0,0.f); v1=fmaxf(v1,0.f); v2=fmaxf(v2,0.f); v3=fmaxf(v3,0.f); }
            if(OUTBF){
                __nv_bfloat16* C=(__nv_bfloat16*)Cout;
                if(r0<M){
                    if(c0<N)   C[(size_t)r0*N+c0]  =__float2bfloat16_rn(v0);
                    if(c0+1<N) C[(size_t)r0*N+c0+1]=__float2bfloat16_rn(v1);
                }
                if(r0+8<M){
                    if(c0<N)   C[(size_t)(r0+8)*N+c0]  =__float2bfloat16_rn(v2);
                    if(c0+1<N) C[(size_t)(r0+8)*N+c0+1]=__float2bfloat16_rn(v3);
                }
            }else{
                float* C=(float*)Cout;
                if(r0<M){
                    if(c0<N)   C[(size_t)r0*N+c0]=v0;
                    if(c0+1<N) C[(size_t)r0*N+c0+1]=v1;
                }
                if(r0+8<M){
                    if(c0<N)   C[(size_t)(r0+8)*N+c0]=v2;
                    if(c0+1<N) C[(size_t)(r0+8)*N+c0+1]=v3;
                }
            }
        }
    }
}

// ========== small bf16 GEMM 128x128x32 (heads) ============================
template<bool OUTBF,bool RELU>
__global__ void __launch_bounds__(256,2)
gemm_bf16(const __nv_bfloat16* __restrict__ A,const __nv_bfloat16* __restrict__ Bw,
          const float* __restrict__ bias,void* __restrict__ Cout,
          int M,int N,int K){
    __shared__ unsigned Ah[2][128*BPADW];
    __shared__ unsigned Bh[2][128*BPADW];
    int tid=threadIdx.x;
    int bm=blockIdx.y*128, bn=blockIdx.x*128;
    int wid=tid>>5, lane=tid&31;
    int wm=wid&3, wn=wid>>2;
    int lr=lane>>2, lc=lane&3;
    float acc[2][8][4];
#pragma unroll
    for(int i=0;i<2;i++)
#pragma unroll
        for(int j=0;j<8;j++)
#pragma unroll
            for(int q=0;q<4;q++) acc[i][j][q]=0.f;
    int arow=tid>>1, ahalf=tid&1;
    int m=bm+arow;
    int bcol=tid>>1, bhalf=tid&1;
    uint4 aV0,aV1,bV0,bV1;
    auto loadG=[&](int k0){
        aV0=make_uint4(0,0,0,0); aV1=aV0;
        if(m<M){
            const __nv_bfloat16* p=A+(size_t)m*K+k0+ahalf*16;
            aV0=*(const uint4*)p; aV1=*(const uint4*)(p+8);
        }
        const __nv_bfloat16* q=Bw+(size_t)(bn+bcol)*K+k0+bhalf*16;
        bV0=*(const uint4*)q; bV1=*(const uint4*)(q+8);
    };
    auto storeS=[&](int stg){
        unsigned* Ad=&Ah[stg][arow*BPADW+ahalf*8];
        *(uint4*)Ad=aV0; *(uint4*)(Ad+4)=aV1;
        unsigned* Bd=&Bh[stg][bcol*BPADW+bhalf*8];
        *(uint4*)Bd=bV0; *(uint4*)(Bd+4)=bV1;
    };
    int T=K>>5;
    loadG(0); storeS(0);
    __syncthreads();
    for(int t=0;t<T;t++){
        int cur=t&1, nxt=cur^1;
        if(t+1<T) loadG((t+1)*32);
        const unsigned* Ac=Ah[cur];
        const unsigned* Bc=Bh[cur];
#pragma unroll
        for(int ks=0;ks<2;ks++){
            int kb=ks*8;
            unsigned af[2][4];
#pragma unroll
            for(int mt=0;mt<2;mt++){
                int r0=wm*32+mt*16+lr;
                af[mt][0]=Ac[r0*BPADW+kb+lc];
                af[mt][1]=Ac[(r0+8)*BPADW+kb+lc];
                af[mt][2]=Ac[r0*BPADW+kb+lc+4];
                af[mt][3]=Ac[(r0+8)*BPADW+kb+lc+4];
            }
#pragma unroll
            for(int nt=0;nt<8;nt++){
                int cb=wn*64+nt*8+lr;
                unsigned b0=Bc[cb*BPADW+kb+lc];
                unsigned b1=Bc[cb*BPADW+kb+lc+4];
#pragma unroll
                for(int mt=0;mt<2;mt++){
                    asm volatile(
                      "mma.sync.aligned.m16n8k16.row.col.f32.bf16.bf16.f32 "
                      "{%0,%1,%2,%3}, {%4,%5,%6,%7}, {%8,%9}, {%0,%1,%2,%3};\n"
                      : "+f"(acc[mt][nt][0]),"+f"(acc[mt][nt][1]),
                        "+f"(acc[mt][nt][2]),"+f"(acc[mt][nt][3])
                      : "r"(af[mt][0]),"r"(af[mt][1]),"r"(af[mt][2]),"r"(af[mt][3]),
                        "r"(b0),"r"(b1));
                }
            }
        }
        if(t+1<T) storeS(nxt);
        __syncthreads();
    }
#pragma unroll
    for(int mt=0;mt<2;mt++){
#pragma unroll
        for(int nt=0;nt<8;nt++){
            int r0=bm+wm*32+mt*16+lr;
            int c0=bn+wn*64+nt*8+lc*2;
            float b0=bias[c0], b1=bias[c0+1];
            float v0=acc[mt][nt][0]+b0, v1=acc[mt][nt][1]+b1;
            float v2=acc[mt][nt][2]+b0, v3=acc[mt][nt][3]+b1;
            if(RELU){ v0=fmaxf(v0,0.f); v1=fmaxf(v1,0.f); v2=fmaxf(v2,0.f); v3=fmaxf(v3,0.f); }
            if(OUTBF){
                __nv_bfloat16* C=(__nv_bfloat16*)Cout;
                if(r0<M){
                    if(c0<N)   C[(size_t)r0*N+c0]  =__float2bfloat16_rn(v0);
                    if(c0+1<N) C[(size_t)r0*N+c0+1]=__float2bfloat16_rn(v1);
                }
                if(r0+8<M){
                    if(c0<N)   C[(size_t)(r0+8)*N+c0]  =__float2bfloat16_rn(v2);
                    if(c0+1<N) C[(size_t)(r0+8)*N+c0+1]=__float2bfloat16_rn(v3);
                }
            }else{
                float* C=(float*)Cout;
                if(r0<M){
                    if(c0<N)   C[(size_t)r0*N+c0]=v0;
                    if(c0+1<N) C[(size_t)r0*N+c0+1]=v1;
                }
                if(r0+8<M){
                    if(c0<N)   C[(size_t)(r0+8)*N+c0]=v2;
                    if(c0+1<N) C[(size_t)(r0+8)*N+c0+1]=v3;
                }
            }
        }
    }
}

__global__ void init_kernel(){
    int i=threadIdx.x;
    if(i<10){ g.tiecntL[i]=0; g.selcntL[i]=0; }
}

// ---------------- fused RPN head (reads bf16 h) ---------------------------
__global__ void rpn_head_all(const float* __restrict__ sw,const float* __restrict__ sb,
    const float* __restrict__ bw,const float* __restrict__ bb){
    __shared__ float wsm[256][16];
    __shared__ float bsm[16];
    int tid=threadIdx.x;
    int lvl=blockIdx.y;
    int H=cH[lvl],W=cW[lvl];
    int HW=H*W, Btot=2*HW;
    for(int i=tid;i<256*16;i+=blockDim.x){
        int c=i>>4, j=i&15;
        float v=0.f;
        if(j<3) v=sw[c*3+j];
        else if(j<15) v=bw[c*12+(j-3)];
        wsm[c][j]=v;
    }
    if(tid<16) bsm[tid]=(tid<3)?sb[tid]:((tid<15)?bb[tid-3]:0.f);
    __syncthreads();
    int m=blockIdx.x*blockDim.x+tid;
    if(m>=Btot) return;
    int b=m/HW, pix=m-b*HW;
    const __nv_bfloat16* hr=g.hb+((size_t)cHOff[lvl]+m)*256;
    int soff=cSOff[lvl];
    float acc[15];
#pragma unroll
    for(int j=0;j<15;j++) acc[j]=0.f;
    for(int c=0;c<256;c+=8){
        uint4 v=*(const uint4*)(hr+c);
        const __nv_bfloat162* pv=(const __nv_bfloat162*)&v;
#pragma unroll
        for(int q=0;q<4;q++){
            float2 f=__bfloat1622float2(pv[q]);
#pragma unroll
            for(int j=0;j<15;j++)
                acc[j]+=f.x*wsm[c+q*2][j]+f.y*wsm[c+q*2+1][j];
        }
    }
    for(int a=0;a<3;a++){
        float lg=acc[a]+bsm[a];
        g.scores[b][soff+pix*3+a]=1.f/(1.f+expf(-lg));
        for(int d=0;d<4;d++)
            g.deltas[b][(size_t)(soff+pix*3+a)*4+d]=acc[3+a*4+d]+bsm[3+a*4+d];
    }
}

// ------------- fused exact stable top-k: grid = 10 instances --------------
__global__ void select_topk_all(){
    int inst=blockIdx.x;
    int lvl=inst>>1, b=inst&1;
    int Nl=cNl5[lvl], k=cK5[lvl];
    const float* s=&g.scores[b][cSOff[lvl]];
    unsigned* hist=g.histL[inst];
    int* tiebuf=g.tiebufL[inst];
    unsigned long long* sbuf=g.sbufL[inst];
    int tid=threadIdx.x;
    __shared__ unsigned csum[1024];
    __shared__ int s_t,s_above,s_u,s_above2;
    if(tid==0){ g.selcntL[inst]=0; g.tiecntL[inst]=0; }
    for(int i=tid;i<65536;i+=1024) __stcg(&hist[i],0u);
    __syncthreads();
    for(int i=tid;i<Nl;i+=1024) atomicAdd(&hist[skey(s[i])>>16],1u);
    __syncthreads();
    {
        unsigned own=0; int base=65535-tid*64;
        for(int q=0;q<64;q++) own+=__ldcg(&hist[base-q]);
        csum[tid]=own; __syncthreads();
        for(int off=1;off<1024;off<<=1){
            unsigned v=csum[tid]; unsigned add=(tid>=off)?csum[tid-off]:0u; __syncthreads();
            csum[tid]=v+add; __syncthreads();
        }
        unsigned excl=csum[tid]-own;
        if(excl<(unsigned)k&&csum[tid]>=(unsigned)k){
            unsigned cum=excl;
            for(int q=0;q<64;q++){
                unsigned c=__ldcg(&hist[base-q]);
                if(cum+c>=(unsigned)k){ s_t=base-q; s_above=(int)cum; break; }
                cum+=c;
            }
        }
        __syncthreads();
    }
    int t=s_t, above=s_above;
    for(int i=tid;i<65536;i+=1024) __stcg(&hist[i],0u);
    __syncthreads();
    for(int i=tid;i<Nl;i+=1024){
        unsigned key=skey(s[i]);
        if((int)(key>>16)==t) atomicAdd(&hist[key&0xFFFFu],1u);
    }
    __syncthreads();
    int need=k-above;
    {
        unsigned own=0; int base=65535-tid*64;
        for(int q=0;q<64;q++) own+=__ldcg(&hist[base-q]);
        csum[tid]=own; __syncthreads();
        for(int off=1;off<1024;off<<=1){
            unsigned v=csum[tid]; unsigned add=(tid>=off)?csum[tid-off]:0u; __syncthreads();
            csum[tid]=v+add; __syncthreads();
        }
        unsigned excl=csum[tid]-own;
        if(excl<(unsigned)need&&csum[tid]>=(unsigned)need){
            unsigned cum=excl;
            for(int q=0;q<64;q++){
                unsigned c=__ldcg(&hist[base-q]);
                if(cum+c>=(unsigned)need){ s_u=base-q; s_above2=(int)cum; break; }
                cum+=c;
            }
        }
        __syncthreads();
    }
    int u=s_u, above2=s_above2;
    unsigned T=(((unsigned)t)<<16)|(unsigned)u;
    for(int i=tid;i<Nl;i+=1024){
        unsigned key=skey(s[i]);
        if(key>T){
            int pos=atomicAdd(&g.selcntL[inst],1);
            sbuf[pos]=(((unsigned long long)key)<<32)|(unsigned)(~(unsigned)i);
        }else if(key==T){
            int p=atomicAdd(&g.tiecntL[inst],1);
            if(p<4096) tiebuf[p]=i;
        }
    }
    __syncthreads();
    int ct=g.tiecntL[inst]; if(ct>4096) ct=4096;
    int mtake=need-above2;
    int pos0=above+above2;
    for(int ti=tid;ti<ct;ti+=1024){
        int myi=tiebuf[ti];
        int rank=0;
        for(int q=0;q<ct;q++) rank+=(tiebuf[q]<myi);
        if(rank<mtake)
            sbuf[pos0+rank]=(((unsigned long long)T)<<32)|(unsigned)(~(unsigned)myi);
    }
    __syncthreads();
    if(tid>=k&&tid<1024) sbuf[tid]=0ull;
}

__global__ void bitonic_lvl(){
    __shared__ unsigned long long a[1024];
    int tid=threadIdx.x;
    a[tid]=g.sbufL[blockIdx.x][tid];
    __syncthreads();
    for(int k=2;k<=1024;k<<=1){
        for(int j=k>>1;j>0;j>>=1){
            int l=tid^j;
            if(l>tid){
                unsigned long long x=a[tid],y=a[l];
                bool sw=((tid&k)==0)?(x<y):(x>y);
                if(sw){ a[tid]=y; a[l]=x; }
            }
            __syncthreads();
        }
    }
    g.sbufL[blockIdx.x][tid]=a[tid];
}

__global__ void rpn_decode_all(const float* __restrict__ iminfo){
    int inst=blockIdx.x;
    int lvl=inst>>1, b=inst&1;
    int k=cK5[lvl], W=cW[lvl];
    int r=threadIdx.x;
    if(r>=k) return;
    unsigned long long key=g.sbufL[inst][r];
    int i=(int)(~(unsigned)key);
    int a=i%3; int pix=i/3; int x=pix%W; int y=pix/W;
    double stride=(double)(1<<(lvl+2));
    double size=8.0*stride;
    double rr=(a==0)?1.0:((a==1)?0.5:2.0);
    double sr=sqrt(rr);
    double hh=size/sr, ww=size*sr;
    double ycd=((double)y+0.5)*stride, xcd=((double)x+0.5)*stride;
    float ya1=(float)(ycd-hh*0.5), xa1=(float)(xcd-ww*0.5);
    float ya2=(float)(ycd+hh*0.5), xa2=(float)(xcd+ww*0.5);
    const float* d=&g.deltas[b][(size_t)(cSOff[lvl]+i)*4];
    float ha=ya2-ya1, wa=xa2-xa1;
    float yc=ya1+0.5f*ha, xc=xa1+0.5f*wa;
    float dy=d[0], dx=d[1];
    float dh=fminf(d[2],CLIPV), dw=fminf(d[3],CLIPV);
    float pcy=dy*ha+yc, pcx=dx*wa+xc;
    float ph=expf(dh)*ha, pw=expf(dw)*wa;
    float hI=iminfo[b*5+0], wI=iminfo[b*5+1];
    g.pbL[inst][r*4+0]=fminf(fmaxf(pcy-0.5f*ph,0.f),hI);
    g.pbL[inst][r*4+1]=fminf(fmaxf(pcx-0.5f*pw,0.f),wI);
    g.pbL[inst][r*4+2]=fminf(fmaxf(pcy+0.5f*ph,0.f),hI);
    g.pbL[inst][r*4+3]=fminf(fmaxf(pcx+0.5f*pw,0.f),wI);
    g.psL[inst][r]=g.scores[b][cSOff[lvl]+i];
}

// ---- RPN NMS: parallel IoU bitmask + single-warp sweep (exact) -----------
__global__ void __launch_bounds__(1024,1) nms_lvl_v2(){
    extern __shared__ float smf[];
    float* y1=smf; float* x1=smf+1024; float* y2=smf+2048; float* x2=smf+3072;
    float* s=smf+4096;
    unsigned* mask=(unsigned*)(smf+5120);
    unsigned* rem=mask+32000;
    int* shoutp=(int*)(rem+32);
    int inst=blockIdx.x;
    int lvl=inst>>1, b=inst&1;
    int k=cK5[lvl], off=cOffCat[lvl];
    int tid=threadIdx.x;
    float* ob=&g.catb[b][off*4];
    float* os=&g.cats[b][off];
    for(int i=tid;i<k;i+=1024){
        y1[i]=g.pbL[inst][i*4+0]; x1[i]=g.pbL[inst][i*4+1];
        y2[i]=g.pbL[inst][i*4+2]; x2[i]=g.pbL[inst][i*4+3];
        s[i]=g.psL[inst][i];
    }
    __syncthreads();
    int nw=(k+31)>>5;
    for(int base=0;base<k;base+=32){
        int i=base+(tid>>5);
        int w=tid&31;
        if(i<k&&w<nw){
            float a1=y1[i],a2=x1[i],a3=y2[i],a4=x2[i];
            float aA=(a3-a1)*(a4-a2);
            unsigned bits=0u;
            int j0=w*32;
            int jmax=min(32,k-j0);
            for(int q=0;q<jmax;q++){
                int j=j0+q;
                float yy1=fmaxf(a1,y1[j]), xx1=fmaxf(a2,x1[j]);
                float yy2=fminf(a3,y2[j]), xx2=fminf(a4,x2[j]);
                float inter=fmaxf(yy2-yy1,0.f)*fmaxf(xx2-xx1,0.f);
                float bA=(y2[j]-y1[j])*(x2[j]-x1[j]);
                float iou=inter/(aA+bA-inter+1e-8f);
                if(iou>=0.7f) bits|=(1u<<q);
            }
            mask[i*32+w]=bits;
        }else if(i<k&&w<32){
            mask[i*32+w]=0u;
        }
    }
    __syncthreads();
    if(tid<32){
        int lane=tid;
        rem[lane]=0u;
        __syncwarp();
        int outp=0;
        for(int i=0;i<k;i++){
            unsigned w=rem[i>>5];
            bool sel=!((w>>(i&31))&1u);
            if(sel){
                rem[lane]|=mask[i*32+lane];
                if(lane==0){
                    os[outp]=s[i];
                    ob[outp*4+0]=y1[i]; ob[outp*4+1]=x1[i];
                    ob[outp*4+2]=y2[i]; ob[outp*4+3]=x2[i];
                }
                outp++;
            }
            __syncwarp();
        }
        if(lane==0)*shoutp=outp;
    }
    __syncthreads();
    int outp=*shoutp;
    for(int r=outp+tid;r<k;r+=1024){
        os[r]=NEGF;
        ob[r*4+0]=0.f; ob[r*4+1]=0.f; ob[r*4+2]=0.f; ob[r*4+3]=0.f;
    }
}

__global__ void cat_rank(){
    __shared__ unsigned long long keys[4819];
    int b=blockIdx.x;
    int tid=threadIdx.x;
    for(int i=tid;i<4819;i+=1024)
        keys[i]=(((unsigned long long)skey(g.cats[b][i]))<<32)|(unsigned)(~(unsigned)i);
    __syncthreads();
    for(int i=tid;i<4819;i+=1024){
        unsigned long long me=keys[i];
        int rank=0;
        for(int j=0;j<4819;j++) rank+=(keys[j]>me);
        if(rank<1000){
            g.rois[b][rank*4+0]=g.catb[b][i*4+0];
            g.rois[b][rank*4+1]=g.catb[b][i*4+1];
            g.rois[b][rank*4+2]=g.catb[b][i*4+2];
            g.rois[b][rank*4+3]=g.catb[b][i*4+3];
        }
    }
}

// -------- ROI align from bf16 feats -> bf16 roifeat -----------------------
__global__ void roialign(){
    int br=blockIdx.x; int b=br/1000;
    int c=threadIdx.x;
    const float* ro=&g.rois[b][(br%1000)*4];
    float y1=ro[0],x1=ro[1],y2=ro[2],x2=ro[3];
    float area=fmaxf((y2-y1)*(x2-x1),1e-6f);
    float lv=floorf(4.f+log2f(sqrtf(area)/224.f));
    lv=fminf(fmaxf(lv,2.f),6.f);
    int li=(int)lv-2;
    int H=cH[li],W=cW[li];
    float Hf=(float)H,Wf=(float)W;
    float stride=cStrideF[li];
    const __nv_bfloat16* base=g.featsbf+((size_t)cHOff[li]+(size_t)b*H*W)*256;
    __nv_bfloat16* outp=&g.roifeatb[(size_t)br*12544];
    for(int p=0;p<49;p++){
        int py=p/7,px=p%7;
        float uy=((float)py+0.5f)/7.f, ux=((float)px+0.5f)/7.f;
        float ys=(y1+(y2-y1)*uy)/stride-0.5f;
        float xs=(x1+(x2-x1)*ux)/stride-0.5f;
        ys=fminf(fmaxf(ys,0.f),Hf-1.f);
        xs=fminf(fmaxf(xs,0.f),Wf-1.f);
        float y0=floorf(ys),x0=floorf(xs);
        float wy=ys-y0,wx=xs-x0;
        int y0i=(int)y0,x0i=(int)x0;
        int y1i=min(y0i+1,H-1),x1i=min(x0i+1,W-1);
        float p00=__bfloat162float(base[((size_t)y0i*W+x0i)*256+c]);
        float p01=__bfloat162float(base[((size_t)y0i*W+x1i)*256+c]);
        float p10=__bfloat162float(base[((size_t)y1i*W+x0i)*256+c]);
        float p11=__bfloat162float(base[((size_t)y1i*W+x1i)*256+c]);
        float w00=(1.f-wy)*(1.f-wx), w01=(1.f-wy)*wx;
        float w10=wy*(1.f-wx), w11=wy*wx;
        float v=p00*w00+p01*w01+p10*w10+p11*w11;
        outp[p*256+c]=__float2bfloat16_rn(v);
    }
}

__global__ void softmax91(){
    int i=blockIdx.x*blockDim.x+threadIdx.x;
    if(i>=2000) return;
    float* p=&g.clsl[(size_t)i*91];
    float mx=p[0];
    for(int c=1;c<91;c++) mx=fmaxf(mx,p[c]);
    float sm=0.f;
    float e[91];
    for(int c=0;c<91;c++){ e[c]=expf(p[c]-mx); sm+=e[c]; }
    for(int c=0;c<91;c++) p[c]=e[c]/sm;
}

__device__ void nms_run(float* y1,float* x1,float* y2,float* x2,float* s,
                        int n,int iters,float th,float* ob,float* os){
    __shared__ float rv[256];
    __shared__ int ri[256];
    __shared__ float cb[4];
    int tid=threadIdx.x;
    for(int it=0;it<iters;it++){
        float bv=-3.0e38f; int bi=1<<30;
        for(int i=tid;i<n;i+=256){
            float v=s[i];
            if(v>bv||(v==bv&&i<bi)){ bv=v; bi=i; }
        }
        rv[tid]=bv; ri[tid]=bi; __syncthreads();
        for(int o=128;o>0;o>>=1){
            if(tid<o){
                float v=rv[tid+o]; int j=ri[tid+o];
                if(v>rv[tid]||(v==rv[tid]&&j<ri[tid])){ rv[tid]=v; ri[tid]=j; }
            }
            __syncthreads();
        }
        int j=ri[0]; float js=rv[0];
        if(js<=NEGF*0.5f){
            for(int r=it+tid;r<iters;r+=256){
                os[r]=NEGF;
                ob[r*4+0]=0.f; ob[r*4+1]=0.f; ob[r*4+2]=0.f; ob[r*4+3]=0.f;
            }
            __syncthreads();
            return;
        }
        if(tid==0){ cb[0]=y1[j]; cb[1]=x1[j]; cb[2]=y2[j]; cb[3]=x2[j]; }
        __syncthreads();
        float a1=cb[0],a2=cb[1],a3=cb[2],a4=cb[3];
        float aA=(a3-a1)*(a4-a2);
        for(int i=tid;i<n;i+=256){
            float yy1=fmaxf(a1,y1[i]), xx1=fmaxf(a2,x1[i]);
            float yy2=fminf(a3,y2[i]), xx2=fminf(a4,x2[i]);
            float inter=fmaxf(yy2-yy1,0.f)*fmaxf(xx2-xx1,0.f);
            float bA=(y2[i]-y1[i])*(x2[i]-x1[i]);
            float iou=inter/(aA+bA-inter+1e-8f);
            if(iou>=th) s[i]=NEGF;
        }
        __syncthreads();
        if(tid==0){
            s[j]=NEGF;
            os[it]=js;
            ob[it*4+0]=a1; ob[it*4+1]=a2; ob[it*4+2]=a3; ob[it*4+3]=a4;
        }
        __syncthreads();
    }
}

__global__ void nms_det(const float* __restrict__ iminfo){
    __shared__ float y1[1000],x1[1000],y2[1000],x2[1000],s[1000];
    int blk=blockIdx.x; int b=blk/90; int c=blk%90+1;
    int tid=threadIdx.x;
    float hI=iminfo[b*5+0], wI=iminfo[b*5+1];
    for(int i=tid;i<1000;i+=256){
        const float* ro=&g.rois[b][i*4];
        float ya1=ro[0],xa1=ro[1],ya2=ro[2],xa2=ro[3];
        float ha=ya2-ya1, wa=xa2-xa1;
        float yc=ya1+0.5f*ha, xc=xa1+0.5f*wa;
        const float* d=&g.boxl[((size_t)(b*1000+i)*91+c)*4];
        float dy=d[0]/10.f, dx=d[1]/10.f;
        float dh=fminf(d[2]/5.f,CLIPV), dw=fminf(d[3]/5.f,CLIPV);
        float pcy=dy*ha+yc, pcx=dx*wa+xc;
        float ph=expf(dh)*ha, pw=expf(dw)*wa;
        y1[i]=fminf(fmaxf(pcy-0.5f*ph,0.f),hI);
        x1[i]=fminf(fmaxf(pcx-0.5f*pw,0.f),wI);
        y2[i]=fminf(fmaxf(pcy+0.5f*ph,0.f),hI);
        x2[i]=fminf(fmaxf(pcx+0.5f*pw,0.f),wI);
        float p=g.clsl[(size_t)(b*1000+i)*91+c];
        s[i]=(p>=0.05f)?p:NEGF;
    }
    __syncthreads();
    nms_run(y1,x1,y2,x2,s,1000,100,0.5f,&g.dnb[b][(c-1)*400],&g.dns[b][(c-1)*100]);
}

__global__ void zero_out(float* out,int out_size){
    int i=blockIdx.x*256+threadIdx.x;
    if(i<out_size) out[i]=0.f;
}

__global__ void det_rank(float* out,int out_size){
    extern __shared__ unsigned long long dk[];
    int b=blockIdx.x;
    int chunk=blockIdx.y;
    int tid=threadIdx.x;
    for(int i=tid;i<9000;i+=1024)
        dk[i]=(((unsigned long long)skey(g.dns[b][i]))<<32)|(unsigned)(~(unsigned)i);
    __syncthreads();
    int i0=chunk*1125, i1=i0+1125;
    for(int i=i0+tid;i<i1;i+=1024){
        unsigned long long me=dk[i];
        int rank=0;
        for(int j=0;j<9000;j++) rank+=(dk[j]>me);
        if(rank<100){
            float sc=g.dns[b][i];
            bool valid=sc>0.f;
            if(valid){
                int ob=2+b*400+rank*4;
                for(int d=0;d<4;d++){
                    int o=ob+d;
                    if(o<out_size) out[o]=g.dnb[b][i*4+d];
                }
                int oc=2+800+b*100+rank;
                if(oc<out_size) out[oc]=(float)(i/100+1);
                int os=2+1000+b*100+rank;
                if(os<out_size) out[os]=sc;
                if(b<out_size) atomicAdd(&out[b],1.f);
            }
        }
    }
}

extern "C" void kernel_launch(void* const* d_in,const int* in_sizes,int n_in,
                              void* d_out,int out_size){
    const float* feats[5];
    for(int i=0;i<5;i++) feats[i]=(const float*)d_in[i];
    const float* iminfo=(const float*)d_in[5];
    const float* cw =(const float*)d_in[6];
    const float* cbv=(const float*)d_in[7];
    const float* sw =(const float*)d_in[8];
    const float* sb =(const float*)d_in[9];
    const float* bw =(const float*)d_in[10];
    const float* bbv=(const float*)d_in[11];
    const float* fc1w=(const float*)d_in[12];
    const float* fc1b=(const float*)d_in[13];
    const float* fc2w=(const float*)d_in[14];
    const float* fc2b=(const float*)d_in[15];
    const float* clsw=(const float*)d_in[16];
    const float* clsb=(const float*)d_in[17];
    const float* boxw=(const float*)d_in[18];
    const float* boxb=(const float*)d_in[19];

    Scratch* gp=nullptr;
    cudaGetSymbolAddress((void**)&gp,g);

    const int BIG_SMEM=(2*256*BPADW+2*128*BPADW)*4;   // 61440 bytes
    static int attr_done=0;
    if(!attr_done){
        cudaFuncSetAttribute(nms_lvl_v2,cudaFuncAttributeMaxDynamicSharedMemorySize,152*1024);
        cudaFuncSetAttribute(det_rank,cudaFuncAttributeMaxDynamicSharedMemorySize,80*1024);
        cudaFuncSetAttribute(gemm_big<2,true,true>,cudaFuncAttributeMaxDynamicSharedMemorySize,BIG_SMEM);
        cudaFuncSetAttribute(gemm_big<0,true,true>,cudaFuncAttributeMaxDynamicSharedMemorySize,BIG_SMEM);
        attr_done=1;
    }
    const int NMS_SMEM=5120*4+32000*4+32*4+16;
    const int DET_SMEM=9000*8;

    init_kernel<<<1,32>>>();                                                         // 0
    cvt_feats<<<dim3(17472,5),256>>>(feats[0],feats[1],feats[2],feats[3],feats[4]);  // 1
    twcvt<<<dim3(72,8),dim3(32,8)>>>(cw,gp->cwT,2304,256,256);                       // 2
    gemm_big<2,true,true><<<dim3(2,728),256,BIG_SMEM>>>(gp->featsbf,gp->cwT,cbv,gp->hb,186186,256,2304); // 3
    rpn_head_all<<<dim3(546,5),256>>>(sw,sb,bw,bbv);                                 // 4
    select_topk_all<<<10,1024>>>();                                                  // 5 (ncu slot)
    bitonic_lvl<<<10,1024>>>();
    rpn_decode_all<<<10,1024>>>(iminfo);
    nms_lvl_v2<<<10,1024,NMS_SMEM>>>();
    cat_rank<<<2,1024>>>();

    roialign<<<2000,256>>>();

    twcvt<<<dim3(392,32),dim3(32,8)>>>(fc1w,gp->fc1wT,12544,1024,1024);
    twcvt<<<dim3(32,32),dim3(32,8)>>>(fc2w,gp->fc2wT,1024,1024,1024);
    twcvt<<<dim3(32,4),dim3(32,8)>>>(clsw,gp->clswT,1024,91,128);
    twcvt<<<dim3(32,12),dim3(32,8)>>>(boxw,gp->boxwT,1024,364,384);
    padbias<<<1,512>>>(clsb,boxb);

    gemm_big<0,true,true><<<dim3(8,8),256,BIG_SMEM>>>(gp->roifeatb,gp->fc1wT,fc1b,gp->h1b,2000,1024,12544);
    gemm_big<0,true,true><<<dim3(8,8),256,BIG_SMEM>>>(gp->h1b,gp->fc2wT,fc2b,gp->h2b,2000,1024,1024);
    gemm_bf16<false,false><<<dim3(1,16),256>>>(gp->h2b,gp->clswT,gp->clsbPad,gp->clsl,2000,91,1024);
    gemm_bf16<false,false><<<dim3(3,16),256>>>(gp->h2b,gp->boxwT,gp->boxbPad,gp->boxl,2000,364,1024);

    softmax91<<<8,256>>>();
    nms_det<<<180,256>>>(iminfo);
    zero_out<<<(out_size+255)/256,256>>>((float*)d_out,out_size);
    det_rank<<<dim3(2,8),1024,DET_SMEM>>>((float*)d_out,out_size);
}

// round 14
// speedup vs baseline: 1.0805x; 1.0805x over previous
#include <cuda_runtime.h>
#include <cuda_bf16.h>
#include <math.h>
#include <stddef.h>

#define NEGF (-1.0e9f)
#define CLIPV 4.135166556742356f

__device__ __forceinline__ unsigned skey(float s){
    unsigned u = __float_as_uint(s);
    return (u & 0x80000000u) ? ~u : (u | 0x80000000u);
}

struct __align__(256) Scratch {
    float scores[2][279280];
    float deltas[2][1117120];
    unsigned histL[10][65536];
    int tiebufL[10][4096];
    int tiecntL[10];
    int selcntL[10];
    unsigned long long sbufL[10][1024];
    float pbL[10][4000];
    float psL[10][1000];
    float catb[2][19280];
    float cats[2][4820];
    float rois[2][4000];
    float clsl[182000];
    float boxl[728000];
    float dns[2][9000];
    float dnb[2][36000];
    float clsbPad[128];
    float boxbPad[384];
    __nv_bfloat16 hb[47663616];
    __nv_bfloat16 featsbf[47663616];
    __nv_bfloat16 cwT[256*2304];
    __nv_bfloat16 fc1wT[1024*12544];
    __nv_bfloat16 fc2wT[1024*1024];
    __nv_bfloat16 clswT[128*1024];
    __nv_bfloat16 boxwT[384*1024];
    __nv_bfloat16 roifeatb[25088000];
    __nv_bfloat16 h1b[2048000];
    __nv_bfloat16 h2b[2048000];
};
__device__ Scratch g;

__constant__ int cH[5]={208,104,52,26,13};
__constant__ int cW[5]={336,168,84,42,21};
__constant__ float cStrideF[5]={4.f,8.f,16.f,32.f,64.f};
__constant__ int cNl5[5]={209664,52416,13104,3276,819};
__constant__ int cK5[5]={1000,1000,1000,1000,819};
__constant__ int cSOff[5]={0,209664,262080,275184,278460};
__constant__ int cHOff[5]={0,139776,174720,183456,185640};
__constant__ int cOffCat[5]={0,1000,2000,3000,4000};

// ---- convert feats fp32 NHWC -> bf16 (per level) --------------------------
__global__ void cvt_feats(const float* f0,const float* f1,const float* f2,
                          const float* f3,const float* f4){
    int lvl=blockIdx.y;
    const float* src=(lvl==0)?f0:(lvl==1)?f1:(lvl==2)?f2:(lvl==3)?f3:f4;
    int Etot=2*cH[lvl]*cW[lvl]*256;
    int base=(blockIdx.x*256+threadIdx.x)*8;
    if(base>=Etot) return;
    float4 a=*(const float4*)(src+base);
    float4 b=*(const float4*)(src+base+4);
    __nv_bfloat162 r0=__floats2bfloat162_rn(a.x,a.y);
    __nv_bfloat162 r1=__floats2bfloat162_rn(a.z,a.w);
    __nv_bfloat162 r2=__floats2bfloat162_rn(b.x,b.y);
    __nv_bfloat162 r3=__floats2bfloat162_rn(b.z,b.w);
    uint4 o=make_uint4(*(unsigned*)&r0,*(unsigned*)&r1,*(unsigned*)&r2,*(unsigned*)&r3);
    *(uint4*)(g.featsbf+(size_t)cHOff[lvl]*256+base)=o;
}

// ---- transpose + convert weights: src[K][N] fp32 -> dst[Npad][K] bf16 -----
__global__ void twcvt(const float* __restrict__ src,__nv_bfloat16* __restrict__ dst,
                      int K,int N,int Npad){
    __shared__ float t[32][33];
    int kb=blockIdx.x*32, nb=blockIdx.y*32;
    int tx=threadIdx.x, ty=threadIdx.y;
#pragma unroll
    for(int d=0;d<4;d++){
        int k=kb+ty+d*8, n=nb+tx;
        t[ty+d*8][tx]=(k<K&&n<N)?src[(size_t)k*N+n]:0.f;
    }
    __syncthreads();
#pragma unroll
    for(int d=0;d<4;d++){
        int n=nb+ty+d*8, k=kb+tx;
        if(n<Npad&&k<K) dst[(size_t)n*K+k]=__float2bfloat16_rn(t[tx][ty+d*8]);
    }
}

__global__ void padbias(const float* clsb,const float* boxb){
    int i=threadIdx.x;
    if(i<128) g.clsbPad[i]=(i<91)?clsb[i]:0.f;
    if(i<384) g.boxbPad[i]=(i<364)?boxb[i]:0.f;
}

// ============ BF16 GEMM 128x128x32 (m16n8k16, fp32 acc), bf16 inputs ======
// MODE 0: dense A[M][K]. MODE 2: fused all-level 3x3 conv over concat M.
// B: bf16 [Npad][K] (pre-transposed). OUTBF: store bf16 else fp32. K%32==0.
#define BPADW 20
template<int MODE,bool OUTBF,bool RELU>
__global__ void __launch_bounds__(256,2)
gemm_bf16(const __nv_bfloat16* __restrict__ A,const __nv_bfloat16* __restrict__ Bw,
          const float* __restrict__ bias,void* __restrict__ Cout,
          int M,int N,int K){
    __shared__ unsigned Ah[2][128*BPADW];
    __shared__ unsigned Bh[2][128*BPADW];
    int tid=threadIdx.x;
    int bm=blockIdx.y*128, bn=blockIdx.x*128;
    int wid=tid>>5, lane=tid&31;
    int wm=wid&3, wn=wid>>2;
    int lr=lane>>2, lc=lane&3;

    float acc[2][8][4];
#pragma unroll
    for(int i=0;i<2;i++)
#pragma unroll
        for(int j=0;j<8;j++)
#pragma unroll
            for(int q=0;q<4;q++) acc[i][j][q]=0.f;

    int arow=tid>>1, ahalf=tid&1;
    int m=bm+arow;
    int ay=0,ax=0,Hl=0,Wl=0; size_t base0=0;
    if(MODE==2){
        int mm=(m<M)?m:0;
        int lvl=(mm>=cHOff[1])+(mm>=cHOff[2])+(mm>=cHOff[3])+(mm>=cHOff[4]);
        Hl=cH[lvl]; Wl=cW[lvl];
        int HW=Hl*Wl;
        int rel=mm-cHOff[lvl];
        int ab=rel/HW; int rem2=rel-ab*HW;
        ay=rem2/Wl; ax=rem2-ay*Wl;
        base0=(size_t)cHOff[lvl]+(size_t)ab*HW;
    }
    int bcol=tid>>1, bhalf=tid&1;

    uint4 aV0,aV1,bV0,bV1;
    auto loadG=[&](int k0){
        aV0=make_uint4(0,0,0,0); aV1=aV0;
        if(m<M){
            if(MODE==0){
                const __nv_bfloat16* p=A+(size_t)m*K+k0+ahalf*16;
                aV0=*(const uint4*)p; aV1=*(const uint4*)(p+8);
            }else{
                int r=k0>>8;
                int ky=r/3, kx=r-ky*3;
                int yy=ay+ky-1, xx=ax+kx-1;
                if(yy>=0&&yy<Hl&&xx>=0&&xx<Wl){
                    const __nv_bfloat16* p=A+(base0+(size_t)yy*Wl+xx)*256+(k0&255)+ahalf*16;
                    aV0=*(const uint4*)p; aV1=*(const uint4*)(p+8);
                }
            }
        }
        const __nv_bfloat16* q=Bw+(size_t)(bn+bcol)*K+k0+bhalf*16;
        bV0=*(const uint4*)q; bV1=*(const uint4*)(q+8);
    };
    auto storeS=[&](int stg){
        unsigned* Ad=&Ah[stg][arow*BPADW+ahalf*8];
        *(uint4*)Ad=aV0; *(uint4*)(Ad+4)=aV1;
        unsigned* Bd=&Bh[stg][bcol*BPADW+bhalf*8];
        *(uint4*)Bd=bV0; *(uint4*)(Bd+4)=bV1;
    };

    int T=K>>5;
    loadG(0); storeS(0);
    __syncthreads();
    for(int t=0;t<T;t++){
        int cur=t&1, nxt=cur^1;
        if(t+1<T) loadG((t+1)*32);
        const unsigned* Ac=Ah[cur];
        const unsigned* Bc=Bh[cur];
#pragma unroll
        for(int ks=0;ks<2;ks++){
            int kb=ks*8;
            unsigned af[2][4];
#pragma unroll
            for(int mt=0;mt<2;mt++){
                int r0=wm*32+mt*16+lr;
                af[mt][0]=Ac[r0*BPADW+kb+lc];
                af[mt][1]=Ac[(r0+8)*BPADW+kb+lc];
                af[mt][2]=Ac[r0*BPADW+kb+lc+4];
                af[mt][3]=Ac[(r0+8)*BPADW+kb+lc+4];
            }
#pragma unroll
            for(int nt=0;nt<8;nt++){
                int cb=wn*64+nt*8+lr;
                unsigned b0=Bc[cb*BPADW+kb+lc];
                unsigned b1=Bc[cb*BPADW+kb+lc+4];
#pragma unroll
                for(int mt=0;mt<2;mt++){
                    asm volatile(
                      "mma.sync.aligned.m16n8k16.row.col.f32.bf16.bf16.f32 "
                      "{%0,%1,%2,%3}, {%4,%5,%6,%7}, {%8,%9}, {%0,%1,%2,%3};\n"
                      : "+f"(acc[mt][nt][0]),"+f"(acc[mt][nt][1]),
                        "+f"(acc[mt][nt][2]),"+f"(acc[mt][nt][3])
                      : "r"(af[mt][0]),"r"(af[mt][1]),"r"(af[mt][2]),"r"(af[mt][3]),
                        "r"(b0),"r"(b1));
                }
            }
        }
        if(t+1<T) storeS(nxt);
        __syncthreads();
    }
#pragma unroll
    for(int mt=0;mt<2;mt++){
#pragma unroll
        for(int nt=0;nt<8;nt++){
            int r0=bm+wm*32+mt*16+lr;
            int c0=bn+wn*64+nt*8+lc*2;
            float b0=bias[c0], b1=bias[c0+1];
            float v0=acc[mt][nt][0]+b0, v1=acc[mt][nt][1]+b1;
            float v2=acc[mt][nt][2]+b0, v3=acc[mt][nt][3]+b1;
            if(RELU){ v0=fmaxf(v0,0.f); v1=fmaxf(v1,0.f); v2=fmaxf(v2,0.f); v3=fmaxf(v3,0.f); }
            if(OUTBF){
                __nv_bfloat16* C=(__nv_bfloat16*)Cout;
                if(r0<M){
                    if(c0<N)   C[(size_t)r0*N+c0]  =__float2bfloat16_rn(v0);
                    if(c0+1<N) C[(size_t)r0*N+c0+1]=__float2bfloat16_rn(v1);
                }
                if(r0+8<M){
                    if(c0<N)   C[(size_t)(r0+8)*N+c0]  =__float2bfloat16_rn(v2);
                    if(c0+1<N) C[(size_t)(r0+8)*N+c0+1]=__float2bfloat16_rn(v3);
                }
            }else{
                float* C=(float*)Cout;
                if(r0<M){
                    if(c0<N)   C[(size_t)r0*N+c0]=v0;
                    if(c0+1<N) C[(size_t)r0*N+c0+1]=v1;
                }
                if(r0+8<M){
                    if(c0<N)   C[(size_t)(r0+8)*N+c0]=v2;
                    if(c0+1<N) C[(size_t)(r0+8)*N+c0+1]=v3;
                }
            }
        }
    }
}

__global__ void init_kernel(){
    int i=threadIdx.x;
    if(i<10){ g.tiecntL[i]=0; g.selcntL[i]=0; }
}

// ---------------- fused RPN head (reads bf16 h) ---------------------------
__global__ void rpn_head_all(const float* __restrict__ sw,const float* __restrict__ sb,
    const float* __restrict__ bw,const float* __restrict__ bb){
    __shared__ float wsm[256][16];
    __shared__ float bsm[16];
    int tid=threadIdx.x;
    int lvl=blockIdx.y;
    int H=cH[lvl],W=cW[lvl];
    int HW=H*W, Btot=2*HW;
    for(int i=tid;i<256*16;i+=blockDim.x){
        int c=i>>4, j=i&15;
        float v=0.f;
        if(j<3) v=sw[c*3+j];
        else if(j<15) v=bw[c*12+(j-3)];
        wsm[c][j]=v;
    }
    if(tid<16) bsm[tid]=(tid<3)?sb[tid]:((tid<15)?bb[tid-3]:0.f);
    __syncthreads();
    int m=blockIdx.x*blockDim.x+tid;
    if(m>=Btot) return;
    int b=m/HW, pix=m-b*HW;
    const __nv_bfloat16* hr=g.hb+((size_t)cHOff[lvl]+m)*256;
    int soff=cSOff[lvl];
    float acc[15];
#pragma unroll
    for(int j=0;j<15;j++) acc[j]=0.f;
    for(int c=0;c<256;c+=8){
        uint4 v=*(const uint4*)(hr+c);
        const __nv_bfloat162* pv=(const __nv_bfloat162*)&v;
#pragma unroll
        for(int q=0;q<4;q++){
            float2 f=__bfloat1622float2(pv[q]);
#pragma unroll
            for(int j=0;j<15;j++)
                acc[j]+=f.x*wsm[c+q*2][j]+f.y*wsm[c+q*2+1][j];
        }
    }
    for(int a=0;a<3;a++){
        float lg=acc[a]+bsm[a];
        g.scores[b][soff+pix*3+a]=1.f/(1.f+expf(-lg));
        for(int d=0;d<4;d++)
            g.deltas[b][(size_t)(soff+pix*3+a)*4+d]=acc[3+a*4+d]+bsm[3+a*4+d];
    }
}

// ------------- fused exact stable top-k: grid = 10 instances --------------
__global__ void select_topk_all(){
    int inst=blockIdx.x;
    int lvl=inst>>1, b=inst&1;
    int Nl=cNl5[lvl], k=cK5[lvl];
    const float* s=&g.scores[b][cSOff[lvl]];
    unsigned* hist=g.histL[inst];
    int* tiebuf=g.tiebufL[inst];
    unsigned long long* sbuf=g.sbufL[inst];
    int tid=threadIdx.x;
    __shared__ unsigned csum[1024];
    __shared__ int s_t,s_above,s_u,s_above2;
    if(tid==0){ g.selcntL[inst]=0; g.tiecntL[inst]=0; }
    for(int i=tid;i<65536;i+=1024) __stcg(&hist[i],0u);
    __syncthreads();
    for(int i=tid;i<Nl;i+=1024) atomicAdd(&hist[skey(s[i])>>16],1u);
    __syncthreads();
    {
        unsigned own=0; int base=65535-tid*64;
        for(int q=0;q<64;q++) own+=__ldcg(&hist[base-q]);
        csum[tid]=own; __syncthreads();
        for(int off=1;off<1024;off<<=1){
            unsigned v=csum[tid]; unsigned add=(tid>=off)?csum[tid-off]:0u; __syncthreads();
            csum[tid]=v+add; __syncthreads();
        }
        unsigned excl=csum[tid]-own;
        if(excl<(unsigned)k&&csum[tid]>=(unsigned)k){
            unsigned cum=excl;
            for(int q=0;q<64;q++){
                unsigned c=__ldcg(&hist[base-q]);
                if(cum+c>=(unsigned)k){ s_t=base-q; s_above=(int)cum; break; }
                cum+=c;
            }
        }
        __syncthreads();
    }
    int t=s_t, above=s_above;
    for(int i=tid;i<65536;i+=1024) __stcg(&hist[i],0u);
    __syncthreads();
    for(int i=tid;i<Nl;i+=1024){
        unsigned key=skey(s[i]);
        if((int)(key>>16)==t) atomicAdd(&hist[key&0xFFFFu],1u);
    }
    __syncthreads();
    int need=k-above;
    {
        unsigned own=0; int base=65535-tid*64;
        for(int q=0;q<64;q++) own+=__ldcg(&hist[base-q]);
        csum[tid]=own; __syncthreads();
        for(int off=1;off<1024;off<<=1){
            unsigned v=csum[tid]; unsigned add=(tid>=off)?csum[tid-off]:0u; __syncthreads();
            csum[tid]=v+add; __syncthreads();
        }
        unsigned excl=csum[tid]-own;
        if(excl<(unsigned)need&&csum[tid]>=(unsigned)need){
            unsigned cum=excl;
            for(int q=0;q<64;q++){
                unsigned c=__ldcg(&hist[base-q]);
                if(cum+c>=(unsigned)need){ s_u=base-q; s_above2=(int)cum; break; }
                cum+=c;
            }
        }
        __syncthreads();
    }
    int u=s_u, above2=s_above2;
    unsigned T=(((unsigned)t)<<16)|(unsigned)u;
    for(int i=tid;i<Nl;i+=1024){
        unsigned key=skey(s[i]);
        if(key>T){
            int pos=atomicAdd(&g.selcntL[inst],1);
            sbuf[pos]=(((unsigned long long)key)<<32)|(unsigned)(~(unsigned)i);
        }else if(key==T){
            int p=atomicAdd(&g.tiecntL[inst],1);
            if(p<4096) tiebuf[p]=i;
        }
    }
    __syncthreads();
    int ct=g.tiecntL[inst]; if(ct>4096) ct=4096;
    int mtake=need-above2;
    int pos0=above+above2;
    for(int ti=tid;ti<ct;ti+=1024){
        int myi=tiebuf[ti];
        int rank=0;
        for(int q=0;q<ct;q++) rank+=(tiebuf[q]<myi);
        if(rank<mtake)
            sbuf[pos0+rank]=(((unsigned long long)T)<<32)|(unsigned)(~(unsigned)myi);
    }
    __syncthreads();
    if(tid>=k&&tid<1024) sbuf[tid]=0ull;
}

__global__ void bitonic_lvl(){
    __shared__ unsigned long long a[1024];
    int tid=threadIdx.x;
    a[tid]=g.sbufL[blockIdx.x][tid];
    __syncthreads();
    for(int k=2;k<=1024;k<<=1){
        for(int j=k>>1;j>0;j>>=1){
            int l=tid^j;
            if(l>tid){
                unsigned long long x=a[tid],y=a[l];
                bool sw=((tid&k)==0)?(x<y):(x>y);
                if(sw){ a[tid]=y; a[l]=x; }
            }
            __syncthreads();
        }
    }
    g.sbufL[blockIdx.x][tid]=a[tid];
}

__global__ void rpn_decode_all(const float* __restrict__ iminfo){
    int inst=blockIdx.x;
    int lvl=inst>>1, b=inst&1;
    int k=cK5[lvl], W=cW[lvl];
    int r=threadIdx.x;
    if(r>=k) return;
    unsigned long long key=g.sbufL[inst][r];
    int i=(int)(~(unsigned)key);
    int a=i%3; int pix=i/3; int x=pix%W; int y=pix/W;
    double stride=(double)(1<<(lvl+2));
    double size=8.0*stride;
    double rr=(a==0)?1.0:((a==1)?0.5:2.0);
    double sr=sqrt(rr);
    double hh=size/sr, ww=size*sr;
    double ycd=((double)y+0.5)*stride, xcd=((double)x+0.5)*stride;
    float ya1=(float)(ycd-hh*0.5), xa1=(float)(xcd-ww*0.5);
    float ya2=(float)(ycd+hh*0.5), xa2=(float)(xcd+ww*0.5);
    const float* d=&g.deltas[b][(size_t)(cSOff[lvl]+i)*4];
    float ha=ya2-ya1, wa=xa2-xa1;
    float yc=ya1+0.5f*ha, xc=xa1+0.5f*wa;
    float dy=d[0], dx=d[1];
    float dh=fminf(d[2],CLIPV), dw=fminf(d[3],CLIPV);
    float pcy=dy*ha+yc, pcx=dx*wa+xc;
    float ph=expf(dh)*ha, pw=expf(dw)*wa;
    float hI=iminfo[b*5+0], wI=iminfo[b*5+1];
    g.pbL[inst][r*4+0]=fminf(fmaxf(pcy-0.5f*ph,0.f),hI);
    g.pbL[inst][r*4+1]=fminf(fmaxf(pcx-0.5f*pw,0.f),wI);
    g.pbL[inst][r*4+2]=fminf(fmaxf(pcy+0.5f*ph,0.f),hI);
    g.pbL[inst][r*4+3]=fminf(fmaxf(pcx+0.5f*pw,0.f),wI);
    g.psL[inst][r]=g.scores[b][cSOff[lvl]+i];
}

// ---- RPN NMS: parallel IoU bitmask + single-warp sweep (exact) -----------
__global__ void __launch_bounds__(1024,1) nms_lvl_v2(){
    extern __shared__ float smf[];
    float* y1=smf; float* x1=smf+1024; float* y2=smf+2048; float* x2=smf+3072;
    float* s=smf+4096;
    unsigned* mask=(unsigned*)(smf+5120);
    unsigned* rem=mask+32000;
    int* shoutp=(int*)(rem+32);
    int inst=blockIdx.x;
    int lvl=inst>>1, b=inst&1;
    int k=cK5[lvl], off=cOffCat[lvl];
    int tid=threadIdx.x;
    float* ob=&g.catb[b][off*4];
    float* os=&g.cats[b][off];
    for(int i=tid;i<k;i+=1024){
        y1[i]=g.pbL[inst][i*4+0]; x1[i]=g.pbL[inst][i*4+1];
        y2[i]=g.pbL[inst][i*4+2]; x2[i]=g.pbL[inst][i*4+3];
        s[i]=g.psL[inst][i];
    }
    __syncthreads();
    int nw=(k+31)>>5;
    for(int base=0;base<k;base+=32){
        int i=base+(tid>>5);
        int w=tid&31;
        if(i<k&&w<nw){
            float a1=y1[i],a2=x1[i],a3=y2[i],a4=x2[i];
            float aA=(a3-a1)*(a4-a2);
            unsigned bits=0u;
            int j0=w*32;
            int jmax=min(32,k-j0);
            for(int q=0;q<jmax;q++){
                int j=j0+q;
                float yy1=fmaxf(a1,y1[j]), xx1=fmaxf(a2,x1[j]);
                float yy2=fminf(a3,y2[j]), xx2=fminf(a4,x2[j]);
                float inter=fmaxf(yy2-yy1,0.f)*fmaxf(xx2-xx1,0.f);
                float bA=(y2[j]-y1[j])*(x2[j]-x1[j]);
                float iou=inter/(aA+bA-inter+1e-8f);
                if(iou>=0.7f) bits|=(1u<<q);
            }
            mask[i*32+w]=bits;
        }else if(i<k&&w<32){
            mask[i*32+w]=0u;
        }
    }
    __syncthreads();
    if(tid<32){
        int lane=tid;
        rem[lane]=0u;
        __syncwarp();
        int outp=0;
        for(int i=0;i<k;i++){
            unsigned w=rem[i>>5];
            bool sel=!((w>>(i&31))&1u);
            if(sel){
                rem[lane]|=mask[i*32+lane];
                if(lane==0){
                    os[outp]=s[i];
                    ob[outp*4+0]=y1[i]; ob[outp*4+1]=x1[i];
                    ob[outp*4+2]=y2[i]; ob[outp*4+3]=x2[i];
                }
                outp++;
            }
            __syncwarp();
        }
        if(lane==0)*shoutp=outp;
    }
    __syncthreads();
    int outp=*shoutp;
    for(int r=outp+tid;r<k;r+=1024){
        os[r]=NEGF;
        ob[r*4+0]=0.f; ob[r*4+1]=0.f; ob[r*4+2]=0.f; ob[r*4+3]=0.f;
    }
}

__global__ void cat_rank(){
    __shared__ unsigned long long keys[4819];
    int b=blockIdx.x;
    int tid=threadIdx.x;
    for(int i=tid;i<4819;i+=1024)
        keys[i]=(((unsigned long long)skey(g.cats[b][i]))<<32)|(unsigned)(~(unsigned)i);
    __syncthreads();
    for(int i=tid;i<4819;i+=1024){
        unsigned long long me=keys[i];
        int rank=0;
        for(int j=0;j<4819;j++) rank+=(keys[j]>me);
        if(rank<1000){
            g.rois[b][rank*4+0]=g.catb[b][i*4+0];
            g.rois[b][rank*4+1]=g.catb[b][i*4+1];
            g.rois[b][rank*4+2]=g.catb[b][i*4+2];
            g.rois[b][rank*4+3]=g.catb[b][i*4+3];
        }
    }
}

// -------- ROI align from bf16 feats -> bf16 roifeat -----------------------
__global__ void roialign(){
    int br=blockIdx.x; int b=br/1000;
    int c=threadIdx.x;
    const float* ro=&g.rois[b][(br%1000)*4];
    float y1=ro[0],x1=ro[1],y2=ro[2],x2=ro[3];
    float area=fmaxf((y2-y1)*(x2-x1),1e-6f);
    float lv=floorf(4.f+log2f(sqrtf(area)/224.f));
    lv=fminf(fmaxf(lv,2.f),6.f);
    int li=(int)lv-2;
    int H=cH[li],W=cW[li];
    float Hf=(float)H,Wf=(float)W;
    float stride=cStrideF[li];
    const __nv_bfloat16* base=g.featsbf+((size_t)cHOff[li]+(size_t)b*H*W)*256;
    __nv_bfloat16* outp=&g.roifeatb[(size_t)br*12544];
    for(int p=0;p<49;p++){
        int py=p/7,px=p%7;
        float uy=((float)py+0.5f)/7.f, ux=((float)px+0.5f)/7.f;
        float ys=(y1+(y2-y1)*uy)/stride-0.5f;
        float xs=(x1+(x2-x1)*ux)/stride-0.5f;
        ys=fminf(fmaxf(ys,0.f),Hf-1.f);
        xs=fminf(fmaxf(xs,0.f),Wf-1.f);
        float y0=floorf(ys),x0=floorf(xs);
        float wy=ys-y0,wx=xs-x0;
        int y0i=(int)y0,x0i=(int)x0;
        int y1i=min(y0i+1,H-1),x1i=min(x0i+1,W-1);
        float p00=__bfloat162float(base[((size_t)y0i*W+x0i)*256+c]);
        float p01=__bfloat162float(base[((size_t)y0i*W+x1i)*256+c]);
        float p10=__bfloat162float(base[((size_t)y1i*W+x0i)*256+c]);
        float p11=__bfloat162float(base[((size_t)y1i*W+x1i)*256+c]);
        float w00=(1.f-wy)*(1.f-wx), w01=(1.f-wy)*wx;
        float w10=wy*(1.f-wx), w11=wy*wx;
        float v=p00*w00+p01*w01+p10*w10+p11*w11;
        outp[p*256+c]=__float2bfloat16_rn(v);
    }
}

__global__ void softmax91(){
    int i=blockIdx.x*blockDim.x+threadIdx.x;
    if(i>=2000) return;
    float* p=&g.clsl[(size_t)i*91];
    float mx=p[0];
    for(int c=1;c<91;c++) mx=fmaxf(mx,p[c]);
    float sm=0.f;
    float e[91];
    for(int c=0;c<91;c++){ e[c]=expf(p[c]-mx); sm+=e[c]; }
    for(int c=0;c<91;c++) p[c]=e[c]/sm;
}

__device__ void nms_run(float* y1,float* x1,float* y2,float* x2,float* s,
                        int n,int iters,float th,float* ob,float* os){
    __shared__ float rv[256];
    __shared__ int ri[256];
    __shared__ float cb[4];
    int tid=threadIdx.x;
    for(int it=0;it<iters;it++){
        float bv=-3.0e38f; int bi=1<<30;
        for(int i=tid;i<n;i+=256){
            float v=s[i];
            if(v>bv||(v==bv&&i<bi)){ bv=v; bi=i; }
        }
        rv[tid]=bv; ri[tid]=bi; __syncthreads();
        for(int o=128;o>0;o>>=1){
            if(tid<o){
                float v=rv[tid+o]; int j=ri[tid+o];
                if(v>rv[tid]||(v==rv[tid]&&j<ri[tid])){ rv[tid]=v; ri[tid]=j; }
            }
            __syncthreads();
        }
        int j=ri[0]; float js=rv[0];
        if(js<=NEGF*0.5f){
            for(int r=it+tid;r<iters;r+=256){
                os[r]=NEGF;
                ob[r*4+0]=0.f; ob[r*4+1]=0.f; ob[r*4+2]=0.f; ob[r*4+3]=0.f;
            }
            __syncthreads();
            return;
        }
        if(tid==0){ cb[0]=y1[j]; cb[1]=x1[j]; cb[2]=y2[j]; cb[3]=x2[j]; }
        __syncthreads();
        float a1=cb[0],a2=cb[1],a3=cb[2],a4=cb[3];
        float aA=(a3-a1)*(a4-a2);
        for(int i=tid;i<n;i+=256){
            float yy1=fmaxf(a1,y1[i]), xx1=fmaxf(a2,x1[i]);
            float yy2=fminf(a3,y2[i]), xx2=fminf(a4,x2[i]);
            float inter=fmaxf(yy2-yy1,0.f)*fmaxf(xx2-xx1,0.f);
            float bA=(y2[i]-y1[i])*(x2[i]-x1[i]);
            float iou=inter/(aA+bA-inter+1e-8f);
            if(iou>=th) s[i]=NEGF;
        }
        __syncthreads();
        if(tid==0){
            s[j]=NEGF;
            os[it]=js;
            ob[it*4+0]=a1; ob[it*4+1]=a2; ob[it*4+2]=a3; ob[it*4+3]=a4;
        }
        __syncthreads();
    }
}

__global__ void nms_det(const float* __restrict__ iminfo){
    __shared__ float y1[1000],x1[1000],y2[1000],x2[1000],s[1000];
    int blk=blockIdx.x; int b=blk/90; int c=blk%90+1;
    int tid=threadIdx.x;
    float hI=iminfo[b*5+0], wI=iminfo[b*5+1];
    for(int i=tid;i<1000;i+=256){
        const float* ro=&g.rois[b][i*4];
        float ya1=ro[0],xa1=ro[1],ya2=ro[2],xa2=ro[3];
        float ha=ya2-ya1, wa=xa2-xa1;
        float yc=ya1+0.5f*ha, xc=xa1+0.5f*wa;
        const float* d=&g.boxl[((size_t)(b*1000+i)*91+c)*4];
        float dy=d[0]/10.f, dx=d[1]/10.f;
        float dh=fminf(d[2]/5.f,CLIPV), dw=fminf(d[3]/5.f,CLIPV);
        float pcy=dy*ha+yc, pcx=dx*wa+xc;
        float ph=expf(dh)*ha, pw=expf(dw)*wa;
        y1[i]=fminf(fmaxf(pcy-0.5f*ph,0.f),hI);
        x1[i]=fminf(fmaxf(pcx-0.5f*pw,0.f),wI);
        y2[i]=fminf(fmaxf(pcy+0.5f*ph,0.f),hI);
        x2[i]=fminf(fmaxf(pcx+0.5f*pw,0.f),wI);
        float p=g.clsl[(size_t)(b*1000+i)*91+c];
        s[i]=(p>=0.05f)?p:NEGF;
    }
    __syncthreads();
    nms_run(y1,x1,y2,x2,s,1000,100,0.5f,&g.dnb[b][(c-1)*400],&g.dns[b][(c-1)*100]);
}

__global__ void zero_out(float* out,int out_size){
    int i=blockIdx.x*256+threadIdx.x;
    if(i<out_size) out[i]=0.f;
}

__global__ void det_rank(float* out,int out_size){
    extern __shared__ unsigned long long dk[];
    int b=blockIdx.x;
    int chunk=blockIdx.y;
    int tid=threadIdx.x;
    for(int i=tid;i<9000;i+=1024)
        dk[i]=(((unsigned long long)skey(g.dns[b][i]))<<32)|(unsigned)(~(unsigned)i);
    __syncthreads();
    int i0=chunk*1125, i1=i0+1125;
    for(int i=i0+tid;i<i1;i+=1024){
        unsigned long long me=dk[i];
        int rank=0;
        for(int j=0;j<9000;j++) rank+=(dk[j]>me);
        if(rank<100){
            float sc=g.dns[b][i];
            bool valid=sc>0.f;
            if(valid){
                int ob=2+b*400+rank*4;
                for(int d=0;d<4;d++){
                    int o=ob+d;
                    if(o<out_size) out[o]=g.dnb[b][i*4+d];
                }
                int oc=2+800+b*100+rank;
                if(oc<out_size) out[oc]=(float)(i/100+1);
                int os=2+1000+b*100+rank;
                if(os<out_size) out[os]=sc;
                if(b<out_size) atomicAdd(&out[b],1.f);
            }
        }
    }
}

extern "C" void kernel_launch(void* const* d_in,const int* in_sizes,int n_in,
                              void* d_out,int out_size){
    const float* feats[5];
    for(int i=0;i<5;i++) feats[i]=(const float*)d_in[i];
    const float* iminfo=(const float*)d_in[5];
    const float* cw =(const float*)d_in[6];
    const float* cbv=(const float*)d_in[7];
    const float* sw =(const float*)d_in[8];
    const float* sb =(const float*)d_in[9];
    const float* bw =(const float*)d_in[10];
    const float* bbv=(const float*)d_in[11];
    const float* fc1w=(const float*)d_in[12];
    const float* fc1b=(const float*)d_in[13];
    const float* fc2w=(const float*)d_in[14];
    const float* fc2b=(const float*)d_in[15];
    const float* clsw=(const float*)d_in[16];
    const float* clsb=(const float*)d_in[17];
    const float* boxw=(const float*)d_in[18];
    const float* boxb=(const float*)d_in[19];

    Scratch* gp=nullptr;
    cudaGetSymbolAddress((void**)&gp,g);

    static int attr_done=0;
    if(!attr_done){
        cudaFuncSetAttribute(nms_lvl_v2,cudaFuncAttributeMaxDynamicSharedMemorySize,152*1024);
        cudaFuncSetAttribute(det_rank,cudaFuncAttributeMaxDynamicSharedMemorySize,80*1024);
        attr_done=1;
    }
    const int NMS_SMEM=5120*4+32000*4+32*4+16;
    const int DET_SMEM=9000*8;

    init_kernel<<<1,32>>>();                                                         // 0
    cvt_feats<<<dim3(17472,5),256>>>(feats[0],feats[1],feats[2],feats[3],feats[4]);  // 1
    twcvt<<<dim3(72,8),dim3(32,8)>>>(cw,gp->cwT,2304,256,256);                       // 2
    gemm_bf16<2,true,true><<<dim3(2,1455),256>>>(gp->featsbf,gp->cwT,cbv,gp->hb,186186,256,2304); // 3
    rpn_head_all<<<dim3(546,5),256>>>(sw,sb,bw,bbv);                                 // 4
    select_topk_all<<<10,1024>>>();                                                  // 5 (ncu slot)
    bitonic_lvl<<<10,1024>>>();
    rpn_decode_all<<<10,1024>>>(iminfo);
    nms_lvl_v2<<<10,1024,NMS_SMEM>>>();
    cat_rank<<<2,1024>>>();

    roialign<<<2000,256>>>();

    twcvt<<<dim3(392,32),dim3(32,8)>>>(fc1w,gp->fc1wT,12544,1024,1024);
    twcvt<<<dim3(32,32),dim3(32,8)>>>(fc2w,gp->fc2wT,1024,1024,1024);
    twcvt<<<dim3(32,4),dim3(32,8)>>>(clsw,gp->clswT,1024,91,128);
    twcvt<<<dim3(32,12),dim3(32,8)>>>(boxw,gp->boxwT,1024,364,384);
    padbias<<<1,512>>>(clsb,boxb);

    gemm_bf16<0,true,true ><<<dim3(8,16),256>>>(gp->roifeatb,gp->fc1wT,fc1b,gp->h1b,2000,1024,12544);
    gemm_bf16<0,true,true ><<<dim3(8,16),256>>>(gp->h1b,gp->fc2wT,fc2b,gp->h2b,2000,1024,1024);
    gemm_bf16<0,false,false><<<dim3(1,16),256>>>(gp->h2b,gp->clswT,gp->clsbPad,gp->clsl,2000,91,1024);
    gemm_bf16<0,false,false><<<dim3(3,16),256>>>(gp->h2b,gp->boxwT,gp->boxbPad,gp->boxl,2000,364,1024);

    softmax91<<<8,256>>>();
    nms_det<<<180,256>>>(iminfo);
    zero_out<<<(out_size+255)/256,256>>>((float*)d_out,out_size);
    det_rank<<<dim3(2,8),1024,DET_SMEM>>>((float*)d_out,out_size);
}

// round 16
// speedup vs baseline: 1.1024x; 1.0203x over previous
#include <cuda_runtime.h>
#include <cuda_bf16.h>
#include <math.h>
#include <stddef.h>

#define NEGF (-1.0e9f)
#define CLIPV 4.135166556742356f

__device__ __forceinline__ unsigned skey(float s){
    unsigned u = __float_as_uint(s);
    return (u & 0x80000000u) ? ~u : (u | 0x80000000u);
}

struct __align__(256) Scratch {
    float scores[2][279280];
    unsigned histL[10][65536];
    int tiebufL[10][4096];
    int tiecntL[10];
    int selcntL[10];
    unsigned long long sbufL[10][1024];
    float pbL[10][4000];
    float psL[10][1000];
    float catb[2][19280];
    float cats[2][4820];
    float rois[2][4000];
    float clsl[182000];
    float boxl[728000];
    float dns[2][9000];
    float dnb[2][36000];
    float clsbPad[128];
    float boxbPad[384];
    __nv_bfloat16 hb[47663616];
    __nv_bfloat16 featsbf[47663616];
    __nv_bfloat16 cwT[256*2304];
    __nv_bfloat16 fc1wT[1024*12544];
    __nv_bfloat16 fc2wT[1024*1024];
    __nv_bfloat16 clswT[128*1024];
    __nv_bfloat16 boxwT[384*1024];
    __nv_bfloat16 roifeatb[25088000];
    __nv_bfloat16 h1b[2048000];
    __nv_bfloat16 h2b[2048000];
};
__device__ Scratch g;

__constant__ int cH[5]={208,104,52,26,13};
__constant__ int cW[5]={336,168,84,42,21};
__constant__ float cStrideF[5]={4.f,8.f,16.f,32.f,64.f};
__constant__ int cNl5[5]={209664,52416,13104,3276,819};
__constant__ int cK5[5]={1000,1000,1000,1000,819};
__constant__ int cSOff[5]={0,209664,262080,275184,278460};
__constant__ int cHOff[5]={0,139776,174720,183456,185640};
__constant__ int cOffCat[5]={0,1000,2000,3000,4000};

// ---- convert feats fp32 NHWC -> bf16 (per level) --------------------------
__global__ void cvt_feats(const float* f0,const float* f1,const float* f2,
                          const float* f3,const float* f4){
    int lvl=blockIdx.y;
    const float* src=(lvl==0)?f0:(lvl==1)?f1:(lvl==2)?f2:(lvl==3)?f3:f4;
    int Etot=2*cH[lvl]*cW[lvl]*256;
    int base=(blockIdx.x*256+threadIdx.x)*8;
    if(base>=Etot) return;
    float4 a=*(const float4*)(src+base);
    float4 b=*(const float4*)(src+base+4);
    __nv_bfloat162 r0=__floats2bfloat162_rn(a.x,a.y);
    __nv_bfloat162 r1=__floats2bfloat162_rn(a.z,a.w);
    __nv_bfloat162 r2=__floats2bfloat162_rn(b.x,b.y);
    __nv_bfloat162 r3=__floats2bfloat162_rn(b.z,b.w);
    uint4 o=make_uint4(*(unsigned*)&r0,*(unsigned*)&r1,*(unsigned*)&r2,*(unsigned*)&r3);
    *(uint4*)(g.featsbf+(size_t)cHOff[lvl]*256+base)=o;
}

// ---- transpose + convert weights: src[K][N] fp32 -> dst[Npad][K] bf16 -----
__global__ void twcvt(const float* __restrict__ src,__nv_bfloat16* __restrict__ dst,
                      int K,int N,int Npad){
    __shared__ float t[32][33];
    int kb=blockIdx.x*32, nb=blockIdx.y*32;
    int tx=threadIdx.x, ty=threadIdx.y;
#pragma unroll
    for(int d=0;d<4;d++){
        int k=kb+ty+d*8, n=nb+tx;
        t[ty+d*8][tx]=(k<K&&n<N)?src[(size_t)k*N+n]:0.f;
    }
    __syncthreads();
#pragma unroll
    for(int d=0;d<4;d++){
        int n=nb+ty+d*8, k=kb+tx;
        if(n<Npad&&k<K) dst[(size_t)n*K+k]=__float2bfloat16_rn(t[tx][ty+d*8]);
    }
}

__global__ void padbias(const float* clsb,const float* boxb){
    int i=threadIdx.x;
    if(i<128) g.clsbPad[i]=(i<91)?clsb[i]:0.f;
    if(i<384) g.boxbPad[i]=(i<364)?boxb[i]:0.f;
}

// ============ BF16 GEMM 128x128x32 (m16n8k16, fp32 acc), bf16 inputs ======
// MODE 0: dense A[M][K]. MODE 2: fused all-level 3x3 conv over concat M.
#define BPADW 20
template<int MODE,bool OUTBF,bool RELU>
__global__ void __launch_bounds__(256,2)
gemm_bf16(const __nv_bfloat16* __restrict__ A,const __nv_bfloat16* __restrict__ Bw,
          const float* __restrict__ bias,void* __restrict__ Cout,
          int M,int N,int K){
    __shared__ unsigned Ah[2][128*BPADW];
    __shared__ unsigned Bh[2][128*BPADW];
    int tid=threadIdx.x;
    int bm=blockIdx.y*128, bn=blockIdx.x*128;
    int wid=tid>>5, lane=tid&31;
    int wm=wid&3, wn=wid>>2;
    int lr=lane>>2, lc=lane&3;

    float acc[2][8][4];
#pragma unroll
    for(int i=0;i<2;i++)
#pragma unroll
        for(int j=0;j<8;j++)
#pragma unroll
            for(int q=0;q<4;q++) acc[i][j][q]=0.f;

    int arow=tid>>1, ahalf=tid&1;
    int m=bm+arow;
    int ay=0,ax=0,Hl=0,Wl=0; size_t base0=0;
    if(MODE==2){
        int mm=(m<M)?m:0;
        int lvl=(mm>=cHOff[1])+(mm>=cHOff[2])+(mm>=cHOff[3])+(mm>=cHOff[4]);
        Hl=cH[lvl]; Wl=cW[lvl];
        int HW=Hl*Wl;
        int rel=mm-cHOff[lvl];
        int ab=rel/HW; int rem2=rel-ab*HW;
        ay=rem2/Wl; ax=rem2-ay*Wl;
        base0=(size_t)cHOff[lvl]+(size_t)ab*HW;
    }
    int bcol=tid>>1, bhalf=tid&1;

    uint4 aV0,aV1,bV0,bV1;
    auto loadG=[&](int k0){
        aV0=make_uint4(0,0,0,0); aV1=aV0;
        if(m<M){
            if(MODE==0){
                const __nv_bfloat16* p=A+(size_t)m*K+k0+ahalf*16;
                aV0=*(const uint4*)p; aV1=*(const uint4*)(p+8);
            }else{
                int r=k0>>8;
                int ky=r/3, kx=r-ky*3;
                int yy=ay+ky-1, xx=ax+kx-1;
                if(yy>=0&&yy<Hl&&xx>=0&&xx<Wl){
                    const __nv_bfloat16* p=A+(base0+(size_t)yy*Wl+xx)*256+(k0&255)+ahalf*16;
                    aV0=*(const uint4*)p; aV1=*(const uint4*)(p+8);
                }
            }
        }
        const __nv_bfloat16* q=Bw+(size_t)(bn+bcol)*K+k0+bhalf*16;
        bV0=*(const uint4*)q; bV1=*(const uint4*)(q+8);
    };
    auto storeS=[&](int stg){
        unsigned* Ad=&Ah[stg][arow*BPADW+ahalf*8];
        *(uint4*)Ad=aV0; *(uint4*)(Ad+4)=aV1;
        unsigned* Bd=&Bh[stg][bcol*BPADW+bhalf*8];
        *(uint4*)Bd=bV0; *(uint4*)(Bd+4)=bV1;
    };

    int T=K>>5;
    loadG(0); storeS(0);
    __syncthreads();
    for(int t=0;t<T;t++){
        int cur=t&1, nxt=cur^1;
        if(t+1<T) loadG((t+1)*32);
        const unsigned* Ac=Ah[cur];
        const unsigned* Bc=Bh[cur];
#pragma unroll
        for(int ks=0;ks<2;ks++){
            int kb=ks*8;
            unsigned af[2][4];
#pragma unroll
            for(int mt=0;mt<2;mt++){
                int r0=wm*32+mt*16+lr;
                af[mt][0]=Ac[r0*BPADW+kb+lc];
                af[mt][1]=Ac[(r0+8)*BPADW+kb+lc];
                af[mt][2]=Ac[r0*BPADW+kb+lc+4];
                af[mt][3]=Ac[(r0+8)*BPADW+kb+lc+4];
            }
#pragma unroll
            for(int nt=0;nt<8;nt++){
                int cb=wn*64+nt*8+lr;
                unsigned b0=Bc[cb*BPADW+kb+lc];
                unsigned b1=Bc[cb*BPADW+kb+lc+4];
#pragma unroll
                for(int mt=0;mt<2;mt++){
                    asm volatile(
                      "mma.sync.aligned.m16n8k16.row.col.f32.bf16.bf16.f32 "
                      "{%0,%1,%2,%3}, {%4,%5,%6,%7}, {%8,%9}, {%0,%1,%2,%3};\n"
                      : "+f"(acc[mt][nt][0]),"+f"(acc[mt][nt][1]),
                        "+f"(acc[mt][nt][2]),"+f"(acc[mt][nt][3])
                      : "r"(af[mt][0]),"r"(af[mt][1]),"r"(af[mt][2]),"r"(af[mt][3]),
                        "r"(b0),"r"(b1));
                }
            }
        }
        if(t+1<T) storeS(nxt);
        __syncthreads();
    }
#pragma unroll
    for(int mt=0;mt<2;mt++){
#pragma unroll
        for(int nt=0;nt<8;nt++){
            int r0=bm+wm*32+mt*16+lr;
            int c0=bn+wn*64+nt*8+lc*2;
            float b0=bias[c0], b1=bias[c0+1];
            float v0=acc[mt][nt][0]+b0, v1=acc[mt][nt][1]+b1;
            float v2=acc[mt][nt][2]+b0, v3=acc[mt][nt][3]+b1;
            if(RELU){ v0=fmaxf(v0,0.f); v1=fmaxf(v1,0.f); v2=fmaxf(v2,0.f); v3=fmaxf(v3,0.f); }
            if(OUTBF){
                __nv_bfloat16* C=(__nv_bfloat16*)Cout;
                if(r0<M){
                    if(c0<N)   C[(size_t)r0*N+c0]  =__float2bfloat16_rn(v0);
                    if(c0+1<N) C[(size_t)r0*N+c0+1]=__float2bfloat16_rn(v1);
                }
                if(r0+8<M){
                    if(c0<N)   C[(size_t)(r0+8)*N+c0]  =__float2bfloat16_rn(v2);
                    if(c0+1<N) C[(size_t)(r0+8)*N+c0+1]=__float2bfloat16_rn(v3);
                }
            }else{
                float* C=(float*)Cout;
                if(r0<M){
                    if(c0<N)   C[(size_t)r0*N+c0]=v0;
                    if(c0+1<N) C[(size_t)r0*N+c0+1]=v1;
                }
                if(r0+8<M){
                    if(c0<N)   C[(size_t)(r0+8)*N+c0]=v2;
                    if(c0+1<N) C[(size_t)(r0+8)*N+c0+1]=v3;
                }
            }
        }
    }
}

__global__ void init_kernel(){
    int i=threadIdx.x;
    if(i<10){ g.tiecntL[i]=0; g.selcntL[i]=0; }
}

// ------- RPN head: SCORES ONLY (deltas recomputed later for top-k) --------
__global__ void rpn_head_scores(const float* __restrict__ sw,const float* __restrict__ sb){
    __shared__ float wsm[256][4];
    __shared__ float bsm[4];
    int tid=threadIdx.x;
    int lvl=blockIdx.y;
    int H=cH[lvl],W=cW[lvl];
    int HW=H*W, Btot=2*HW;
    for(int i=tid;i<256*4;i+=blockDim.x){
        int c=i>>2, j=i&3;
        wsm[c][j]=(j<3)?sw[c*3+j]:0.f;
    }
    if(tid<4) bsm[tid]=(tid<3)?sb[tid]:0.f;
    __syncthreads();
    int m=blockIdx.x*blockDim.x+tid;
    if(m>=Btot) return;
    int b=m/HW, pix=m-b*HW;
    const __nv_bfloat16* hr=g.hb+((size_t)cHOff[lvl]+m)*256;
    int soff=cSOff[lvl];
    float acc[3];
#pragma unroll
    for(int j=0;j<3;j++) acc[j]=0.f;
    for(int c=0;c<256;c+=8){
        uint4 v=*(const uint4*)(hr+c);
        const __nv_bfloat162* pv=(const __nv_bfloat162*)&v;
#pragma unroll
        for(int q=0;q<4;q++){
            float2 f=__bfloat1622float2(pv[q]);
#pragma unroll
            for(int j=0;j<3;j++)
                acc[j]+=f.x*wsm[c+q*2][j]+f.y*wsm[c+q*2+1][j];
        }
    }
    for(int a=0;a<3;a++){
        float lg=acc[a]+bsm[a];
        g.scores[b][soff+pix*3+a]=1.f/(1.f+expf(-lg));
    }
}

// ------------- fused exact stable top-k: grid = 10 instances --------------
__global__ void select_topk_all(){
    int inst=blockIdx.x;
    int lvl=inst>>1, b=inst&1;
    int Nl=cNl5[lvl], k=cK5[lvl];
    const float* s=&g.scores[b][cSOff[lvl]];
    unsigned* hist=g.histL[inst];
    int* tiebuf=g.tiebufL[inst];
    unsigned long long* sbuf=g.sbufL[inst];
    int tid=threadIdx.x;
    __shared__ unsigned csum[1024];
    __shared__ int s_t,s_above,s_u,s_above2;
    if(tid==0){ g.selcntL[inst]=0; g.tiecntL[inst]=0; }
    for(int i=tid;i<65536;i+=1024) __stcg(&hist[i],0u);
    __syncthreads();
    for(int i=tid;i<Nl;i+=1024) atomicAdd(&hist[skey(s[i])>>16],1u);
    __syncthreads();
    {
        unsigned own=0; int base=65535-tid*64;
        for(int q=0;q<64;q++) own+=__ldcg(&hist[base-q]);
        csum[tid]=own; __syncthreads();
        for(int off=1;off<1024;off<<=1){
            unsigned v=csum[tid]; unsigned add=(tid>=off)?csum[tid-off]:0u; __syncthreads();
            csum[tid]=v+add; __syncthreads();
        }
        unsigned excl=csum[tid]-own;
        if(excl<(unsigned)k&&csum[tid]>=(unsigned)k){
            unsigned cum=excl;
            for(int q=0;q<64;q++){
                unsigned c=__ldcg(&hist[base-q]);
                if(cum+c>=(unsigned)k){ s_t=base-q; s_above=(int)cum; break; }
                cum+=c;
            }
        }
        __syncthreads();
    }
    int t=s_t, above=s_above;
    for(int i=tid;i<65536;i+=1024) __stcg(&hist[i],0u);
    __syncthreads();
    for(int i=tid;i<Nl;i+=1024){
        unsigned key=skey(s[i]);
        if((int)(key>>16)==t) atomicAdd(&hist[key&0xFFFFu],1u);
    }
    __syncthreads();
    int need=k-above;
    {
        unsigned own=0; int base=65535-tid*64;
        for(int q=0;q<64;q++) own+=__ldcg(&hist[base-q]);
        csum[tid]=own; __syncthreads();
        for(int off=1;off<1024;off<<=1){
            unsigned v=csum[tid]; unsigned add=(tid>=off)?csum[tid-off]:0u; __syncthreads();
            csum[tid]=v+add; __syncthreads();
        }
        unsigned excl=csum[tid]-own;
        if(excl<(unsigned)need&&csum[tid]>=(unsigned)need){
            unsigned cum=excl;
            for(int q=0;q<64;q++){
                unsigned c=__ldcg(&hist[base-q]);
                if(cum+c>=(unsigned)need){ s_u=base-q; s_above2=(int)cum; break; }
                cum+=c;
            }
        }
        __syncthreads();
    }
    int u=s_u, above2=s_above2;
    unsigned T=(((unsigned)t)<<16)|(unsigned)u;
    for(int i=tid;i<Nl;i+=1024){
        unsigned key=skey(s[i]);
        if(key>T){
            int pos=atomicAdd(&g.selcntL[inst],1);
            sbuf[pos]=(((unsigned long long)key)<<32)|(unsigned)(~(unsigned)i);
        }else if(key==T){
            int p=atomicAdd(&g.tiecntL[inst],1);
            if(p<4096) tiebuf[p]=i;
        }
    }
    __syncthreads();
    int ct=g.tiecntL[inst]; if(ct>4096) ct=4096;
    int mtake=need-above2;
    int pos0=above+above2;
    for(int ti=tid;ti<ct;ti+=1024){
        int myi=tiebuf[ti];
        int rank=0;
        for(int q=0;q<ct;q++) rank+=(tiebuf[q]<myi);
        if(rank<mtake)
            sbuf[pos0+rank]=(((unsigned long long)T)<<32)|(unsigned)(~(unsigned)myi);
    }
    __syncthreads();
    if(tid>=k&&tid<1024) sbuf[tid]=0ull;
}

__global__ void bitonic_lvl(){
    __shared__ unsigned long long a[1024];
    int tid=threadIdx.x;
    a[tid]=g.sbufL[blockIdx.x][tid];
    __syncthreads();
    for(int k=2;k<=1024;k<<=1){
        for(int j=k>>1;j>0;j>>=1){
            int l=tid^j;
            if(l>tid){
                unsigned long long x=a[tid],y=a[l];
                bool sw=((tid&k)==0)?(x<y):(x>y);
                if(sw){ a[tid]=y; a[l]=x; }
            }
            __syncthreads();
        }
    }
    g.sbufL[blockIdx.x][tid]=a[tid];
}

// ---- decode: recompute the 4 box-delta dots for selected anchors only ----
__global__ void rpn_decode_all(const float* __restrict__ iminfo,
                               const float* __restrict__ bw,const float* __restrict__ bb){
    __shared__ float wsm[256][12];
    __shared__ float bsm[12];
    int inst=blockIdx.x;
    int lvl=inst>>1, b=inst&1;
    int k=cK5[lvl], W=cW[lvl];
    int tid=threadIdx.x;
    for(int i=tid;i<256*12;i+=1024){
        int c=i/12, j=i%12;
        wsm[c][j]=bw[c*12+j];
    }
    if(tid<12) bsm[tid]=bb[tid];
    __syncthreads();
    int r=tid;
    if(r>=k) return;
    unsigned long long key=g.sbufL[inst][r];
    int i=(int)(~(unsigned)key);
    int a=i%3; int pix=i/3; int x=pix%W; int y=pix/W;
    // recompute 4 deltas for this anchor (identical expression to old head)
    int HW=cH[lvl]*cW[lvl];
    const __nv_bfloat16* hr=g.hb+((size_t)cHOff[lvl]+(size_t)b*HW+pix)*256;
    float acc[4];
#pragma unroll
    for(int j=0;j<4;j++) acc[j]=0.f;
    for(int c=0;c<256;c+=8){
        uint4 v=*(const uint4*)(hr+c);
        const __nv_bfloat162* pv=(const __nv_bfloat162*)&v;
#pragma unroll
        for(int q=0;q<4;q++){
            float2 f=__bfloat1622float2(pv[q]);
#pragma unroll
            for(int j=0;j<4;j++)
                acc[j]+=f.x*wsm[c+q*2][a*4+j]+f.y*wsm[c+q*2+1][a*4+j];
        }
    }
    float dl[4];
#pragma unroll
    for(int j=0;j<4;j++) dl[j]=acc[j]+bsm[a*4+j];

    double stride=(double)(1<<(lvl+2));
    double size=8.0*stride;
    double rr=(a==0)?1.0:((a==1)?0.5:2.0);
    double sr=sqrt(rr);
    double hh=size/sr, ww=size*sr;
    double ycd=((double)y+0.5)*stride, xcd=((double)x+0.5)*stride;
    float ya1=(float)(ycd-hh*0.5), xa1=(float)(xcd-ww*0.5);
    float ya2=(float)(ycd+hh*0.5), xa2=(float)(xcd+ww*0.5);
    float ha=ya2-ya1, wa=xa2-xa1;
    float yc=ya1+0.5f*ha, xc=xa1+0.5f*wa;
    float dy=dl[0], dx=dl[1];
    float dh=fminf(dl[2],CLIPV), dw=fminf(dl[3],CLIPV);
    float pcy=dy*ha+yc, pcx=dx*wa+xc;
    float ph=expf(dh)*ha, pw=expf(dw)*wa;
    float hI=iminfo[b*5+0], wI=iminfo[b*5+1];
    g.pbL[inst][r*4+0]=fminf(fmaxf(pcy-0.5f*ph,0.f),hI);
    g.pbL[inst][r*4+1]=fminf(fmaxf(pcx-0.5f*pw,0.f),wI);
    g.pbL[inst][r*4+2]=fminf(fmaxf(pcy+0.5f*ph,0.f),hI);
    g.pbL[inst][r*4+3]=fminf(fmaxf(pcx+0.5f*pw,0.f),wI);
    g.psL[inst][r]=g.scores[b][cSOff[lvl]+i];
}

// ---- RPN NMS: parallel IoU bitmask + single-warp sweep (exact) -----------
__global__ void __launch_bounds__(1024,1) nms_lvl_v2(){
    extern __shared__ float smf[];
    float* y1=smf; float* x1=smf+1024; float* y2=smf+2048; float* x2=smf+3072;
    float* s=smf+4096;
    unsigned* mask=(unsigned*)(smf+5120);
    unsigned* rem=mask+32000;
    int* shoutp=(int*)(rem+32);
    int inst=blockIdx.x;
    int lvl=inst>>1, b=inst&1;
    int k=cK5[lvl], off=cOffCat[lvl];
    int tid=threadIdx.x;
    float* ob=&g.catb[b][off*4];
    float* os=&g.cats[b][off];
    for(int i=tid;i<k;i+=1024){
        y1[i]=g.pbL[inst][i*4+0]; x1[i]=g.pbL[inst][i*4+1];
        y2[i]=g.pbL[inst][i*4+2]; x2[i]=g.pbL[inst][i*4+3];
        s[i]=g.psL[inst][i];
    }
    __syncthreads();
    int nw=(k+31)>>5;
    for(int base=0;base<k;base+=32){
        int i=base+(tid>>5);
        int w=tid&31;
        if(i<k&&w<nw){
            float a1=y1[i],a2=x1[i],a3=y2[i],a4=x2[i];
            float aA=(a3-a1)*(a4-a2);
            unsigned bits=0u;
            int j0=w*32;
            int jmax=min(32,k-j0);
            for(int q=0;q<jmax;q++){
                int j=j0+q;
                float yy1=fmaxf(a1,y1[j]), xx1=fmaxf(a2,x1[j]);
                float yy2=fminf(a3,y2[j]), xx2=fminf(a4,x2[j]);
                float inter=fmaxf(yy2-yy1,0.f)*fmaxf(xx2-xx1,0.f);
                float bA=(y2[j]-y1[j])*(x2[j]-x1[j]);
                float iou=inter/(aA+bA-inter+1e-8f);
                if(iou>=0.7f) bits|=(1u<<q);
            }
            mask[i*32+w]=bits;
        }else if(i<k&&w<32){
            mask[i*32+w]=0u;
        }
    }
    __syncthreads();
    if(tid<32){
        int lane=tid;
        rem[lane]=0u;
        __syncwarp();
        int outp=0;
        for(int i=0;i<k;i++){
            unsigned w=rem[i>>5];
            bool sel=!((w>>(i&31))&1u);
            if(sel){
                rem[lane]|=mask[i*32+lane];
                if(lane==0){
                    os[outp]=s[i];
                    ob[outp*4+0]=y1[i]; ob[outp*4+1]=x1[i];
                    ob[outp*4+2]=y2[i]; ob[outp*4+3]=x2[i];
                }
                outp++;
            }
            __syncwarp();
        }
        if(lane==0)*shoutp=outp;
    }
    __syncthreads();
    int outp=*shoutp;
    for(int r=outp+tid;r<k;r+=1024){
        os[r]=NEGF;
        ob[r*4+0]=0.f; ob[r*4+1]=0.f; ob[r*4+2]=0.f; ob[r*4+3]=0.f;
    }
}

__global__ void cat_rank(){
    __shared__ unsigned long long keys[4819];
    int b=blockIdx.x;
    int tid=threadIdx.x;
    for(int i=tid;i<4819;i+=1024)
        keys[i]=(((unsigned long long)skey(g.cats[b][i]))<<32)|(unsigned)(~(unsigned)i);
    __syncthreads();
    for(int i=tid;i<4819;i+=1024){
        unsigned long long me=keys[i];
        int rank=0;
        for(int j=0;j<4819;j++) rank+=(keys[j]>me);
        if(rank<1000){
            g.rois[b][rank*4+0]=g.catb[b][i*4+0];
            g.rois[b][rank*4+1]=g.catb[b][i*4+1];
            g.rois[b][rank*4+2]=g.catb[b][i*4+2];
            g.rois[b][rank*4+3]=g.catb[b][i*4+3];
        }
    }
}

// -------- ROI align from bf16 feats -> bf16 roifeat (2 ch/thread) ---------
__global__ void roialign(){
    int br=blockIdx.x; int b=br/1000;
    int c2=threadIdx.x;           // 128 threads, channel pair
    const float* ro=&g.rois[b][(br%1000)*4];
    float y1=ro[0],x1=ro[1],y2=ro[2],x2=ro[3];
    float area=fmaxf((y2-y1)*(x2-x1),1e-6f);
    float lv=floorf(4.f+log2f(sqrtf(area)/224.f));
    lv=fminf(fmaxf(lv,2.f),6.f);
    int li=(int)lv-2;
    int H=cH[li],W=cW[li];
    float Hf=(float)H,Wf=(float)W;
    float stride=cStrideF[li];
    const __nv_bfloat16* base=g.featsbf+((size_t)cHOff[li]+(size_t)b*H*W)*256;
    __nv_bfloat16* outp=&g.roifeatb[(size_t)br*12544];
    for(int p=0;p<49;p++){
        int py=p/7,px=p%7;
        float uy=((float)py+0.5f)/7.f, ux=((float)px+0.5f)/7.f;
        float ys=(y1+(y2-y1)*uy)/stride-0.5f;
        float xs=(x1+(x2-x1)*ux)/stride-0.5f;
        ys=fminf(fmaxf(ys,0.f),Hf-1.f);
        xs=fminf(fmaxf(xs,0.f),Wf-1.f);
        float y0=floorf(ys),x0=floorf(xs);
        float wy=ys-y0,wx=xs-x0;
        int y0i=(int)y0,x0i=(int)x0;
        int y1i=min(y0i+1,H-1),x1i=min(x0i+1,W-1);
        float2 p00=__bfloat1622float2(*(const __nv_bfloat162*)(base+((size_t)y0i*W+x0i)*256+c2*2));
        float2 p01=__bfloat1622float2(*(const __nv_bfloat162*)(base+((size_t)y0i*W+x1i)*256+c2*2));
        float2 p10=__bfloat1622float2(*(const __nv_bfloat162*)(base+((size_t)y1i*W+x0i)*256+c2*2));
        float2 p11=__bfloat1622float2(*(const __nv_bfloat162*)(base+((size_t)y1i*W+x1i)*256+c2*2));
        float w00=(1.f-wy)*(1.f-wx), w01=(1.f-wy)*wx;
        float w10=wy*(1.f-wx), w11=wy*wx;
        float vx=p00.x*w00+p01.x*w01+p10.x*w10+p11.x*w11;
        float vy=p00.y*w00+p01.y*w01+p10.y*w10+p11.y*w11;
        *(__nv_bfloat162*)(outp+p*256+c2*2)=__floats2bfloat162_rn(vx,vy);
    }
}

__global__ void softmax91(){
    int i=blockIdx.x*blockDim.x+threadIdx.x;
    if(i>=2000) return;
    float* p=&g.clsl[(size_t)i*91];
    float mx=p[0];
    for(int c=1;c<91;c++) mx=fmaxf(mx,p[c]);
    float sm=0.f;
    float e[91];
    for(int c=0;c<91;c++){ e[c]=expf(p[c]-mx); sm+=e[c]; }
    for(int c=0;c<91;c++) p[c]=e[c]/sm;
}

__device__ void nms_run(float* y1,float* x1,float* y2,float* x2,float* s,
                        int n,int iters,float th,float* ob,float* os){
    __shared__ float rv[256];
    __shared__ int ri[256];
    __shared__ float cb[4];
    int tid=threadIdx.x;
    for(int it=0;it<iters;it++){
        float bv=-3.0e38f; int bi=1<<30;
        for(int i=tid;i<n;i+=256){
            float v=s[i];
            if(v>bv||(v==bv&&i<bi)){ bv=v; bi=i; }
        }
        rv[tid]=bv; ri[tid]=bi; __syncthreads();
        for(int o=128;o>0;o>>=1){
            if(tid<o){
                float v=rv[tid+o]; int j=ri[tid+o];
                if(v>rv[tid]||(v==rv[tid]&&j<ri[tid])){ rv[tid]=v; ri[tid]=j; }
            }
            __syncthreads();
        }
        int j=ri[0]; float js=rv[0];
        if(js<=NEGF*0.5f){
            for(int r=it+tid;r<iters;r+=256){
                os[r]=NEGF;
                ob[r*4+0]=0.f; ob[r*4+1]=0.f; ob[r*4+2]=0.f; ob[r*4+3]=0.f;
            }
            __syncthreads();
            return;
        }
        if(tid==0){ cb[0]=y1[j]; cb[1]=x1[j]; cb[2]=y2[j]; cb[3]=x2[j]; }
        __syncthreads();
        float a1=cb[0],a2=cb[1],a3=cb[2],a4=cb[3];
        float aA=(a3-a1)*(a4-a2);
        for(int i=tid;i<n;i+=256){
            float yy1=fmaxf(a1,y1[i]), xx1=fmaxf(a2,x1[i]);
            float yy2=fminf(a3,y2[i]), xx2=fminf(a4,x2[i]);
            float inter=fmaxf(yy2-yy1,0.f)*fmaxf(xx2-xx1,0.f);
            float bA=(y2[i]-y1[i])*(x2[i]-x1[i]);
            float iou=inter/(aA+bA-inter+1e-8f);
            if(iou>=th) s[i]=NEGF;
        }
        __syncthreads();
        if(tid==0){
            s[j]=NEGF;
            os[it]=js;
            ob[it*4+0]=a1; ob[it*4+1]=a2; ob[it*4+2]=a3; ob[it*4+3]=a4;
        }
        __syncthreads();
    }
}

__global__ void nms_det(const float* __restrict__ iminfo){
    __shared__ float y1[1000],x1[1000],y2[1000],x2[1000],s[1000];
    int blk=blockIdx.x; int b=blk/90; int c=blk%90+1;
    int tid=threadIdx.x;
    float hI=iminfo[b*5+0], wI=iminfo[b*5+1];
    for(int i=tid;i<1000;i+=256){
        const float* ro=&g.rois[b][i*4];
        float ya1=ro[0],xa1=ro[1],ya2=ro[2],xa2=ro[3];
        float ha=ya2-ya1, wa=xa2-xa1;
        float yc=ya1+0.5f*ha, xc=xa1+0.5f*wa;
        const float* d=&g.boxl[((size_t)(b*1000+i)*91+c)*4];
        float dy=d[0]/10.f, dx=d[1]/10.f;
        float dh=fminf(d[2]/5.f,CLIPV), dw=fminf(d[3]/5.f,CLIPV);
        float pcy=dy*ha+yc, pcx=dx*wa+xc;
        float ph=expf(dh)*ha, pw=expf(dw)*wa;
        y1[i]=fminf(fmaxf(pcy-0.5f*ph,0.f),hI);
        x1[i]=fminf(fmaxf(pcx-0.5f*pw,0.f),wI);
        y2[i]=fminf(fmaxf(pcy+0.5f*ph,0.f),hI);
        x2[i]=fminf(fmaxf(pcx+0.5f*pw,0.f),wI);
        float p=g.clsl[(size_t)(b*1000+i)*91+c];
        s[i]=(p>=0.05f)?p:NEGF;
    }
    __syncthreads();
    nms_run(y1,x1,y2,x2,s,1000,100,0.5f,&g.dnb[b][(c-1)*400],&g.dns[b][(c-1)*100]);
}

__global__ void zero_out(float* out,int out_size){
    int i=blockIdx.x*256+threadIdx.x;
    if(i<out_size) out[i]=0.f;
}

__global__ void det_rank(float* out,int out_size){
    extern __shared__ unsigned long long dk[];
    int b=blockIdx.x;
    int chunk=blockIdx.y;
    int tid=threadIdx.x;
    for(int i=tid;i<9000;i+=1024)
        dk[i]=(((unsigned long long)skey(g.dns[b][i]))<<32)|(unsigned)(~(unsigned)i);
    __syncthreads();
    int i0=chunk*1125, i1=i0+1125;
    for(int i=i0+tid;i<i1;i+=1024){
        unsigned long long me=dk[i];
        int rank=0;
        for(int j=0;j<9000;j++) rank+=(dk[j]>me);
        if(rank<100){
            float sc=g.dns[b][i];
            bool valid=sc>0.f;
            if(valid){
                int ob=2+b*400+rank*4;
                for(int d=0;d<4;d++){
                    int o=ob+d;
                    if(o<out_size) out[o]=g.dnb[b][i*4+d];
                }
                int oc=2+800+b*100+rank;
                if(oc<out_size) out[oc]=(float)(i/100+1);
                int os=2+1000+b*100+rank;
                if(os<out_size) out[os]=sc;
                if(b<out_size) atomicAdd(&out[b],1.f);
            }
        }
    }
}

extern "C" void kernel_launch(void* const* d_in,const int* in_sizes,int n_in,
                              void* d_out,int out_size){
    const float* feats[5];
    for(int i=0;i<5;i++) feats[i]=(const float*)d_in[i];
    const float* iminfo=(const float*)d_in[5];
    const float* cw =(const float*)d_in[6];
    const float* cbv=(const float*)d_in[7];
    const float* sw =(const float*)d_in[8];
    const float* sb =(const float*)d_in[9];
    const float* bw =(const float*)d_in[10];
    const float* bbv=(const float*)d_in[11];
    const float* fc1w=(const float*)d_in[12];
    const float* fc1b=(const float*)d_in[13];
    const float* fc2w=(const float*)d_in[14];
    const float* fc2b=(const float*)d_in[15];
    const float* clsw=(const float*)d_in[16];
    const float* clsb=(const float*)d_in[17];
    const float* boxw=(const float*)d_in[18];
    const float* boxb=(const float*)d_in[19];

    Scratch* gp=nullptr;
    cudaGetSymbolAddress((void**)&gp,g);

    static int attr_done=0;
    if(!attr_done){
        cudaFuncSetAttribute(nms_lvl_v2,cudaFuncAttributeMaxDynamicSharedMemorySize,152*1024);
        cudaFuncSetAttribute(det_rank,cudaFuncAttributeMaxDynamicSharedMemorySize,80*1024);
        attr_done=1;
    }
    const int NMS_SMEM=5120*4+32000*4+32*4+16;
    const int DET_SMEM=9000*8;

    init_kernel<<<1,32>>>();
    cvt_feats<<<dim3(17472,5),256>>>(feats[0],feats[1],feats[2],feats[3],feats[4]);
    twcvt<<<dim3(72,8),dim3(32,8)>>>(cw,gp->cwT,2304,256,256);
    gemm_bf16<2,true,true><<<dim3(2,1455),256>>>(gp->featsbf,gp->cwT,cbv,gp->hb,186186,256,2304);
    rpn_head_scores<<<dim3(546,5),256>>>(sw,sb);
    select_topk_all<<<10,1024>>>();
    bitonic_lvl<<<10,1024>>>();
    rpn_decode_all<<<10,1024>>>(iminfo,bw,bbv);
    nms_lvl_v2<<<10,1024,NMS_SMEM>>>();
    cat_rank<<<2,1024>>>();

    roialign<<<2000,128>>>();

    twcvt<<<dim3(392,32),dim3(32,8)>>>(fc1w,gp->fc1wT,12544,1024,1024);
    twcvt<<<dim3(32,32),dim3(32,8)>>>(fc2w,gp->fc2wT,1024,1024,1024);
    twcvt<<<dim3(32,4),dim3(32,8)>>>(clsw,gp->clswT,1024,91,128);
    twcvt<<<dim3(32,12),dim3(32,8)>>>(boxw,gp->boxwT,1024,364,384);
    padbias<<<1,512>>>(clsb,boxb);

    gemm_bf16<0,true,true ><<<dim3(8,16),256>>>(gp->roifeatb,gp->fc1wT,fc1b,gp->h1b,2000,1024,12544);
    gemm_bf16<0,true,true ><<<dim3(8,16),256>>>(gp->h1b,gp->fc2wT,fc2b,gp->h2b,2000,1024,1024);
    gemm_bf16<0,false,false><<<dim3(1,16),256>>>(gp->h2b,gp->clswT,gp->clsbPad,gp->clsl,2000,91,1024);
    gemm_bf16<0,false,false><<<dim3(3,16),256>>>(gp->h2b,gp->boxwT,gp->boxbPad,gp->boxl,2000,364,1024);

    softmax91<<<8,256>>>();
    nms_det<<<180,256>>>(iminfo);
    zero_out<<<(out_size+255)/256,256>>>((float*)d_out,out_size);
    det_rank<<<dim3(2,8),1024,DET_SMEM>>>((float*)d_out,out_size);
}

// round 17
// speedup vs baseline: 1.1357x; 1.0303x over previous
#include <cuda_runtime.h>
#include <cuda_bf16.h>
#include <math.h>
#include <stddef.h>

#define NEGF (-1.0e9f)
#define CLIPV 4.135166556742356f

__device__ __forceinline__ unsigned skey(float s){
    unsigned u = __float_as_uint(s);
    return (u & 0x80000000u) ? ~u : (u | 0x80000000u);
}

struct __align__(256) Scratch {
    float scores[2][279280];
    unsigned histL[10][65536];
    int tiebufL[10][4096];
    int tiecntL[10];
    int selcntL[10];
    unsigned long long sbufL[10][1024];
    float pbL[10][4000];
    float psL[10][1000];
    float catb[2][19280];
    float cats[2][4820];
    float rois[2][4000];
    float clsl[182000];
    float boxl[728000];
    float dns[2][9000];
    float dnb[2][36000];
    float clsbPad[128];
    float boxbPad[384];
    __nv_bfloat16 hb[47663616];
    __nv_bfloat16 featsbf[47663616];
    __nv_bfloat16 cwT[256*2304];
    __nv_bfloat16 fc1wT[1024*12544];
    __nv_bfloat16 fc2wT[1024*1024];
    __nv_bfloat16 clswT[128*1024];
    __nv_bfloat16 boxwT[384*1024];
    __nv_bfloat16 roifeatb[25088000];
    __nv_bfloat16 h1b[2048000];
    __nv_bfloat16 h2b[2048000];
};
__device__ Scratch g;

__constant__ int cH[5]={208,104,52,26,13};
__constant__ int cW[5]={336,168,84,42,21};
__constant__ float cStrideF[5]={4.f,8.f,16.f,32.f,64.f};
__constant__ int cNl5[5]={209664,52416,13104,3276,819};
__constant__ int cK5[5]={1000,1000,1000,1000,819};
__constant__ int cSOff[5]={0,209664,262080,275184,278460};
__constant__ int cHOff[5]={0,139776,174720,183456,185640};
__constant__ int cOffCat[5]={0,1000,2000,3000,4000};

// ---- convert feats fp32 NHWC -> bf16 (per level) --------------------------
__global__ void cvt_feats(const float* f0,const float* f1,const float* f2,
                          const float* f3,const float* f4){
    int lvl=blockIdx.y;
    const float* src=(lvl==0)?f0:(lvl==1)?f1:(lvl==2)?f2:(lvl==3)?f3:f4;
    int Etot=2*cH[lvl]*cW[lvl]*256;
    int base=(blockIdx.x*256+threadIdx.x)*8;
    if(base>=Etot) return;
    float4 a=*(const float4*)(src+base);
    float4 b=*(const float4*)(src+base+4);
    __nv_bfloat162 r0=__floats2bfloat162_rn(a.x,a.y);
    __nv_bfloat162 r1=__floats2bfloat162_rn(a.z,a.w);
    __nv_bfloat162 r2=__floats2bfloat162_rn(b.x,b.y);
    __nv_bfloat162 r3=__floats2bfloat162_rn(b.z,b.w);
    uint4 o=make_uint4(*(unsigned*)&r0,*(unsigned*)&r1,*(unsigned*)&r2,*(unsigned*)&r3);
    *(uint4*)(g.featsbf+(size_t)cHOff[lvl]*256+base)=o;
}

// ---- transpose + convert weights: src[K][N] fp32 -> dst[Npad][K] bf16 -----
__global__ void twcvt(const float* __restrict__ src,__nv_bfloat16* __restrict__ dst,
                      int K,int N,int Npad){
    __shared__ float t[32][33];
    int kb=blockIdx.x*32, nb=blockIdx.y*32;
    int tx=threadIdx.x, ty=threadIdx.y;
#pragma unroll
    for(int d=0;d<4;d++){
        int k=kb+ty+d*8, n=nb+tx;
        t[ty+d*8][tx]=(k<K&&n<N)?src[(size_t)k*N+n]:0.f;
    }
    __syncthreads();
#pragma unroll
    for(int d=0;d<4;d++){
        int n=nb+ty+d*8, k=kb+tx;
        if(n<Npad&&k<K) dst[(size_t)n*K+k]=__float2bfloat16_rn(t[tx][ty+d*8]);
    }
}

__global__ void padbias(const float* clsb,const float* boxb){
    int i=threadIdx.x;
    if(i<128) g.clsbPad[i]=(i<91)?clsb[i]:0.f;
    if(i<384) g.boxbPad[i]=(i<364)?boxb[i]:0.f;
}

// ============ BF16 GEMM 128x128x32 (m16n8k16, fp32 acc), bf16 inputs ======
// MODE 0: dense A[M][K]. MODE 2: fused all-level 3x3 conv over concat M.
// Fragment loads via ldmatrix.m8n8.x4 (conflict-free with BPADW=20).
#define BPADW 20
template<int MODE,bool OUTBF,bool RELU>
__global__ void __launch_bounds__(256,2)
gemm_bf16(const __nv_bfloat16* __restrict__ A,const __nv_bfloat16* __restrict__ Bw,
          const float* __restrict__ bias,void* __restrict__ Cout,
          int M,int N,int K){
    __shared__ unsigned Ah[2][128*BPADW];
    __shared__ unsigned Bh[2][128*BPADW];
    int tid=threadIdx.x;
    int bm=blockIdx.y*128, bn=blockIdx.x*128;
    int wid=tid>>5, lane=tid&31;
    int wm=wid&3, wn=wid>>2;
    int lr=lane>>2, lc=lane&3;

    float acc[2][8][4];
#pragma unroll
    for(int i=0;i<2;i++)
#pragma unroll
        for(int j=0;j<8;j++)
#pragma unroll
            for(int q=0;q<4;q++) acc[i][j][q]=0.f;

    int arow=tid>>1, ahalf=tid&1;
    int m=bm+arow;
    int ay=0,ax=0,Hl=0,Wl=0; size_t base0=0;
    if(MODE==2){
        int mm=(m<M)?m:0;
        int lvl=(mm>=cHOff[1])+(mm>=cHOff[2])+(mm>=cHOff[3])+(mm>=cHOff[4]);
        Hl=cH[lvl]; Wl=cW[lvl];
        int HW=Hl*Wl;
        int rel=mm-cHOff[lvl];
        int ab=rel/HW; int rem2=rel-ab*HW;
        ay=rem2/Wl; ax=rem2-ay*Wl;
        base0=(size_t)cHOff[lvl]+(size_t)ab*HW;
    }
    int bcol=tid>>1, bhalf=tid&1;

    // ldmatrix lane geometry
    int laneA_row=(lane&7)+(lane&8);        // 0..15
    int laneA_k=(lane&16)?4:0;
    int laneB_row=(lane&7)+((lane&16)>>1);  // 0..15
    int laneB_k=(lane&8)?4:0;

    uint4 aV0,aV1,bV0,bV1;
    auto loadG=[&](int k0){
        aV0=make_uint4(0,0,0,0); aV1=aV0;
        if(m<M){
            if(MODE==0){
                const __nv_bfloat16* p=A+(size_t)m*K+k0+ahalf*16;
                aV0=*(const uint4*)p; aV1=*(const uint4*)(p+8);
            }else{
                int r=k0>>8;
                int ky=r/3, kx=r-ky*3;
                int yy=ay+ky-1, xx=ax+kx-1;
                if(yy>=0&&yy<Hl&&xx>=0&&xx<Wl){
                    const __nv_bfloat16* p=A+(base0+(size_t)yy*Wl+xx)*256+(k0&255)+ahalf*16;
                    aV0=*(const uint4*)p; aV1=*(const uint4*)(p+8);
                }
            }
        }
        const __nv_bfloat16* q=Bw+(size_t)(bn+bcol)*K+k0+bhalf*16;
        bV0=*(const uint4*)q; bV1=*(const uint4*)(q+8);
    };
    auto storeS=[&](int stg){
        unsigned* Ad=&Ah[stg][arow*BPADW+ahalf*8];
        *(uint4*)Ad=aV0; *(uint4*)(Ad+4)=aV1;
        unsigned* Bd=&Bh[stg][bcol*BPADW+bhalf*8];
        *(uint4*)Bd=bV0; *(uint4*)(Bd+4)=bV1;
    };

    int T=K>>5;
    loadG(0); storeS(0);
    __syncthreads();
    for(int t=0;t<T;t++){
        int cur=t&1, nxt=cur^1;
        if(t+1<T) loadG((t+1)*32);
        const unsigned* Ac=Ah[cur];
        const unsigned* Bc=Bh[cur];
#pragma unroll
        for(int ks=0;ks<2;ks++){
            int kb=ks*8;
            unsigned af[2][4];
#pragma unroll
            for(int mt=0;mt<2;mt++){
                unsigned adr=(unsigned)__cvta_generic_to_shared(
                    &Ac[(wm*32+mt*16+laneA_row)*BPADW+kb+laneA_k]);
                asm volatile("ldmatrix.sync.aligned.m8n8.x4.shared.b16 {%0,%1,%2,%3},[%4];"
                    : "=r"(af[mt][0]),"=r"(af[mt][1]),"=r"(af[mt][2]),"=r"(af[mt][3])
                    : "r"(adr));
            }
            unsigned bf0[8],bf1[8];
#pragma unroll
            for(int ntp=0;ntp<4;ntp++){
                unsigned adr=(unsigned)__cvta_generic_to_shared(
                    &Bc[(wn*64+ntp*16+laneB_row)*BPADW+kb+laneB_k]);
                asm volatile("ldmatrix.sync.aligned.m8n8.x4.shared.b16 {%0,%1,%2,%3},[%4];"
                    : "=r"(bf0[2*ntp]),"=r"(bf1[2*ntp]),"=r"(bf0[2*ntp+1]),"=r"(bf1[2*ntp+1])
                    : "r"(adr));
            }
#pragma unroll
            for(int nt=0;nt<8;nt++){
#pragma unroll
                for(int mt=0;mt<2;mt++){
                    asm volatile(
                      "mma.sync.aligned.m16n8k16.row.col.f32.bf16.bf16.f32 "
                      "{%0,%1,%2,%3}, {%4,%5,%6,%7}, {%8,%9}, {%0,%1,%2,%3};\n"
                      : "+f"(acc[mt][nt][0]),"+f"(acc[mt][nt][1]),
                        "+f"(acc[mt][nt][2]),"+f"(acc[mt][nt][3])
                      : "r"(af[mt][0]),"r"(af[mt][1]),"r"(af[mt][2]),"r"(af[mt][3]),
                        "r"(bf0[nt]),"r"(bf1[nt]));
                }
            }
        }
        if(t+1<T) storeS(nxt);
        __syncthreads();
    }
#pragma unroll
    for(int mt=0;mt<2;mt++){
#pragma unroll
        for(int nt=0;nt<8;nt++){
            int r0=bm+wm*32+mt*16+lr;
            int c0=bn+wn*64+nt*8+lc*2;
            float b0=bias[c0], b1=bias[c0+1];
            float v0=acc[mt][nt][0]+b0, v1=acc[mt][nt][1]+b1;
            float v2=acc[mt][nt][2]+b0, v3=acc[mt][nt][3]+b1;
            if(RELU){ v0=fmaxf(v0,0.f); v1=fmaxf(v1,0.f); v2=fmaxf(v2,0.f); v3=fmaxf(v3,0.f); }
            if(OUTBF){
                __nv_bfloat16* C=(__nv_bfloat16*)Cout;
                if(r0<M){
                    if(c0<N)   C[(size_t)r0*N+c0]  =__float2bfloat16_rn(v0);
                    if(c0+1<N) C[(size_t)r0*N+c0+1]=__float2bfloat16_rn(v1);
                }
                if(r0+8<M){
                    if(c0<N)   C[(size_t)(r0+8)*N+c0]  =__float2bfloat16_rn(v2);
                    if(c0+1<N) C[(size_t)(r0+8)*N+c0+1]=__float2bfloat16_rn(v3);
                }
            }else{
                float* C=(float*)Cout;
                if(r0<M){
                    if(c0<N)   C[(size_t)r0*N+c0]=v0;
                    if(c0+1<N) C[(size_t)r0*N+c0+1]=v1;
                }
                if(r0+8<M){
                    if(c0<N)   C[(size_t)(r0+8)*N+c0]=v2;
                    if(c0+1<N) C[(size_t)(r0+8)*N+c0+1]=v3;
                }
            }
        }
    }
}

__global__ void init_kernel(){
    int i=threadIdx.x;
    if(i<10){ g.tiecntL[i]=0; g.selcntL[i]=0; }
}

// ------- RPN head: SCORES ONLY --------------------------------------------
__global__ void rpn_head_scores(const float* __restrict__ sw,const float* __restrict__ sb){
    __shared__ float wsm[256][4];
    __shared__ float bsm[4];
    int tid=threadIdx.x;
    int lvl=blockIdx.y;
    int H=cH[lvl],W=cW[lvl];
    int HW=H*W, Btot=2*HW;
    for(int i=tid;i<256*4;i+=blockDim.x){
        int c=i>>2, j=i&3;
        wsm[c][j]=(j<3)?sw[c*3+j]:0.f;
    }
    if(tid<4) bsm[tid]=(tid<3)?sb[tid]:0.f;
    __syncthreads();
    int m=blockIdx.x*blockDim.x+tid;
    if(m>=Btot) return;
    int b=m/HW, pix=m-b*HW;
    const __nv_bfloat16* hr=g.hb+((size_t)cHOff[lvl]+m)*256;
    int soff=cSOff[lvl];
    float acc[3];
#pragma unroll
    for(int j=0;j<3;j++) acc[j]=0.f;
    for(int c=0;c<256;c+=8){
        uint4 v=*(const uint4*)(hr+c);
        const __nv_bfloat162* pv=(const __nv_bfloat162*)&v;
#pragma unroll
        for(int q=0;q<4;q++){
            float2 f=__bfloat1622float2(pv[q]);
#pragma unroll
            for(int j=0;j<3;j++)
                acc[j]+=f.x*wsm[c+q*2][j]+f.y*wsm[c+q*2+1][j];
        }
    }
    for(int a=0;a<3;a++){
        float lg=acc[a]+bsm[a];
        g.scores[b][soff+pix*3+a]=1.f/(1.f+expf(-lg));
    }
}

// ------------- fused exact stable top-k: grid = 10 instances --------------
__global__ void select_topk_all(){
    int inst=blockIdx.x;
    int lvl=inst>>1, b=inst&1;
    int Nl=cNl5[lvl], k=cK5[lvl];
    const float* s=&g.scores[b][cSOff[lvl]];
    unsigned* hist=g.histL[inst];
    int* tiebuf=g.tiebufL[inst];
    unsigned long long* sbuf=g.sbufL[inst];
    int tid=threadIdx.x;
    __shared__ unsigned csum[1024];
    __shared__ int s_t,s_above,s_u,s_above2;
    if(tid==0){ g.selcntL[inst]=0; g.tiecntL[inst]=0; }
    for(int i=tid;i<65536;i+=1024) __stcg(&hist[i],0u);
    __syncthreads();
    for(int i=tid;i<Nl;i+=1024) atomicAdd(&hist[skey(s[i])>>16],1u);
    __syncthreads();
    {
        unsigned own=0; int base=65535-tid*64;
        for(int q=0;q<64;q++) own+=__ldcg(&hist[base-q]);
        csum[tid]=own; __syncthreads();
        for(int off=1;off<1024;off<<=1){
            unsigned v=csum[tid]; unsigned add=(tid>=off)?csum[tid-off]:0u; __syncthreads();
            csum[tid]=v+add; __syncthreads();
        }
        unsigned excl=csum[tid]-own;
        if(excl<(unsigned)k&&csum[tid]>=(unsigned)k){
            unsigned cum=excl;
            for(int q=0;q<64;q++){
                unsigned c=__ldcg(&hist[base-q]);
                if(cum+c>=(unsigned)k){ s_t=base-q; s_above=(int)cum; break; }
                cum+=c;
            }
        }
        __syncthreads();
    }
    int t=s_t, above=s_above;
    for(int i=tid;i<65536;i+=1024) __stcg(&hist[i],0u);
    __syncthreads();
    for(int i=tid;i<Nl;i+=1024){
        unsigned key=skey(s[i]);
        if((int)(key>>16)==t) atomicAdd(&hist[key&0xFFFFu],1u);
    }
    __syncthreads();
    int need=k-above;
    {
        unsigned own=0; int base=65535-tid*64;
        for(int q=0;q<64;q++) own+=__ldcg(&hist[base-q]);
        csum[tid]=own; __syncthreads();
        for(int off=1;off<1024;off<<=1){
            unsigned v=csum[tid]; unsigned add=(tid>=off)?csum[tid-off]:0u; __syncthreads();
            csum[tid]=v+add; __syncthreads();
        }
        unsigned excl=csum[tid]-own;
        if(excl<(unsigned)need&&csum[tid]>=(unsigned)need){
            unsigned cum=excl;
            for(int q=0;q<64;q++){
                unsigned c=__ldcg(&hist[base-q]);
                if(cum+c>=(unsigned)need){ s_u=base-q; s_above2=(int)cum; break; }
                cum+=c;
            }
        }
        __syncthreads();
    }
    int u=s_u, above2=s_above2;
    unsigned T=(((unsigned)t)<<16)|(unsigned)u;
    for(int i=tid;i<Nl;i+=1024){
        unsigned key=skey(s[i]);
        if(key>T){
            int pos=atomicAdd(&g.selcntL[inst],1);
            sbuf[pos]=(((unsigned long long)key)<<32)|(unsigned)(~(unsigned)i);
        }else if(key==T){
            int p=atomicAdd(&g.tiecntL[inst],1);
            if(p<4096) tiebuf[p]=i;
        }
    }
    __syncthreads();
    int ct=g.tiecntL[inst]; if(ct>4096) ct=4096;
    int mtake=need-above2;
    int pos0=above+above2;
    for(int ti=tid;ti<ct;ti+=1024){
        int myi=tiebuf[ti];
        int rank=0;
        for(int q=0;q<ct;q++) rank+=(tiebuf[q]<myi);
        if(rank<mtake)
            sbuf[pos0+rank]=(((unsigned long long)T)<<32)|(unsigned)(~(unsigned)myi);
    }
    __syncthreads();
    if(tid>=k&&tid<1024) sbuf[tid]=0ull;
}

__global__ void bitonic_lvl(){
    __shared__ unsigned long long a[1024];
    int tid=threadIdx.x;
    a[tid]=g.sbufL[blockIdx.x][tid];
    __syncthreads();
    for(int k=2;k<=1024;k<<=1){
        for(int j=k>>1;j>0;j>>=1){
            int l=tid^j;
            if(l>tid){
                unsigned long long x=a[tid],y=a[l];
                bool sw=((tid&k)==0)?(x<y):(x>y);
                if(sw){ a[tid]=y; a[l]=x; }
            }
            __syncthreads();
        }
    }
    g.sbufL[blockIdx.x][tid]=a[tid];
}

// ---- decode: recompute the 4 box-delta dots for selected anchors only ----
__global__ void rpn_decode_all(const float* __restrict__ iminfo,
                               const float* __restrict__ bw,const float* __restrict__ bb){
    __shared__ float wsm[256][12];
    __shared__ float bsm[12];
    int inst=blockIdx.x;
    int lvl=inst>>1, b=inst&1;
    int k=cK5[lvl], W=cW[lvl];
    int tid=threadIdx.x;
    for(int i=tid;i<256*12;i+=1024){
        int c=i/12, j=i%12;
        wsm[c][j]=bw[c*12+j];
    }
    if(tid<12) bsm[tid]=bb[tid];
    __syncthreads();
    int r=tid;
    if(r>=k) return;
    unsigned long long key=g.sbufL[inst][r];
    int i=(int)(~(unsigned)key);
    int a=i%3; int pix=i/3; int x=pix%W; int y=pix/W;
    int HW=cH[lvl]*cW[lvl];
    const __nv_bfloat16* hr=g.hb+((size_t)cHOff[lvl]+(size_t)b*HW+pix)*256;
    float acc[4];
#pragma unroll
    for(int j=0;j<4;j++) acc[j]=0.f;
    for(int c=0;c<256;c+=8){
        uint4 v=*(const uint4*)(hr+c);
        const __nv_bfloat162* pv=(const __nv_bfloat162*)&v;
#pragma unroll
        for(int q=0;q<4;q++){
            float2 f=__bfloat1622float2(pv[q]);
#pragma unroll
            for(int j=0;j<4;j++)
                acc[j]+=f.x*wsm[c+q*2][a*4+j]+f.y*wsm[c+q*2+1][a*4+j];
        }
    }
    float dl[4];
#pragma unroll
    for(int j=0;j<4;j++) dl[j]=acc[j]+bsm[a*4+j];

    double stride=(double)(1<<(lvl+2));
    double size=8.0*stride;
    double rr=(a==0)?1.0:((a==1)?0.5:2.0);
    double sr=sqrt(rr);
    double hh=size/sr, ww=size*sr;
    double ycd=((double)y+0.5)*stride, xcd=((double)x+0.5)*stride;
    float ya1=(float)(ycd-hh*0.5), xa1=(float)(xcd-ww*0.5);
    float ya2=(float)(ycd+hh*0.5), xa2=(float)(xcd+ww*0.5);
    float ha=ya2-ya1, wa=xa2-xa1;
    float yc=ya1+0.5f*ha, xc=xa1+0.5f*wa;
    float dy=dl[0], dx=dl[1];
    float dh=fminf(dl[2],CLIPV), dw=fminf(dl[3],CLIPV);
    float pcy=dy*ha+yc, pcx=dx*wa+xc;
    float ph=expf(dh)*ha, pw=expf(dw)*wa;
    float hI=iminfo[b*5+0], wI=iminfo[b*5+1];
    g.pbL[inst][r*4+0]=fminf(fmaxf(pcy-0.5f*ph,0.f),hI);
    g.pbL[inst][r*4+1]=fminf(fmaxf(pcx-0.5f*pw,0.f),wI);
    g.pbL[inst][r*4+2]=fminf(fmaxf(pcy+0.5f*ph,0.f),hI);
    g.pbL[inst][r*4+3]=fminf(fmaxf(pcx+0.5f*pw,0.f),wI);
    g.psL[inst][r]=g.scores[b][cSOff[lvl]+i];
}

// ---- RPN NMS: parallel IoU bitmask + single-warp sweep (exact) -----------
__global__ void __launch_bounds__(1024,1) nms_lvl_v2(){
    extern __shared__ float smf[];
    float* y1=smf; float* x1=smf+1024; float* y2=smf+2048; float* x2=smf+3072;
    float* s=smf+4096;
    unsigned* mask=(unsigned*)(smf+5120);
    unsigned* rem=mask+32000;
    int* shoutp=(int*)(rem+32);
    int inst=blockIdx.x;
    int lvl=inst>>1, b=inst&1;
    int k=cK5[lvl], off=cOffCat[lvl];
    int tid=threadIdx.x;
    float* ob=&g.catb[b][off*4];
    float* os=&g.cats[b][off];
    for(int i=tid;i<k;i+=1024){
        y1[i]=g.pbL[inst][i*4+0]; x1[i]=g.pbL[inst][i*4+1];
        y2[i]=g.pbL[inst][i*4+2]; x2[i]=g.pbL[inst][i*4+3];
        s[i]=g.psL[inst][i];
    }
    __syncthreads();
    int nw=(k+31)>>5;
    for(int base=0;base<k;base+=32){
        int i=base+(tid>>5);
        int w=tid&31;
        if(i<k&&w<nw){
            float a1=y1[i],a2=x1[i],a3=y2[i],a4=x2[i];
            float aA=(a3-a1)*(a4-a2);
            unsigned bits=0u;
            int j0=w*32;
            int jmax=min(32,k-j0);
            for(int q=0;q<jmax;q++){
                int j=j0+q;
                float yy1=fmaxf(a1,y1[j]), xx1=fmaxf(a2,x1[j]);
                float yy2=fminf(a3,y2[j]), xx2=fminf(a4,x2[j]);
                float inter=fmaxf(yy2-yy1,0.f)*fmaxf(xx2-xx1,0.f);
                float bA=(y2[j]-y1[j])*(x2[j]-x1[j]);
                float iou=inter/(aA+bA-inter+1e-8f);
                if(iou>=0.7f) bits|=(1u<<q);
            }
            mask[i*32+w]=bits;
        }else if(i<k&&w<32){
            mask[i*32+w]=0u;
        }
    }
    __syncthreads();
    if(tid<32){
        int lane=tid;
        rem[lane]=0u;
        __syncwarp();
        int outp=0;
        for(int i=0;i<k;i++){
            unsigned w=rem[i>>5];
            bool sel=!((w>>(i&31))&1u);
            if(sel){
                rem[lane]|=mask[i*32+lane];
                if(lane==0){
                    os[outp]=s[i];
                    ob[outp*4+0]=y1[i]; ob[outp*4+1]=x1[i];
                    ob[outp*4+2]=y2[i]; ob[outp*4+3]=x2[i];
                }
                outp++;
            }
            __syncwarp();
        }
        if(lane==0)*shoutp=outp;
    }
    __syncthreads();
    int outp=*shoutp;
    for(int r=outp+tid;r<k;r+=1024){
        os[r]=NEGF;
        ob[r*4+0]=0.f; ob[r*4+1]=0.f; ob[r*4+2]=0.f; ob[r*4+3]=0.f;
    }
}

__global__ void cat_rank(){
    __shared__ unsigned long long keys[4819];
    int b=blockIdx.x;
    int tid=threadIdx.x;
    for(int i=tid;i<4819;i+=1024)
        keys[i]=(((unsigned long long)skey(g.cats[b][i]))<<32)|(unsigned)(~(unsigned)i);
    __syncthreads();
    for(int i=tid;i<4819;i+=1024){
        unsigned long long me=keys[i];
        int rank=0;
        for(int j=0;j<4819;j++) rank+=(keys[j]>me);
        if(rank<1000){
            g.rois[b][rank*4+0]=g.catb[b][i*4+0];
            g.rois[b][rank*4+1]=g.catb[b][i*4+1];
            g.rois[b][rank*4+2]=g.catb[b][i*4+2];
            g.rois[b][rank*4+3]=g.catb[b][i*4+3];
        }
    }
}

// -------- ROI align from bf16 feats -> bf16 roifeat (2 ch/thread) ---------
__global__ void roialign(){
    int br=blockIdx.x; int b=br/1000;
    int c2=threadIdx.x;
    const float* ro=&g.rois[b][(br%1000)*4];
    float y1=ro[0],x1=ro[1],y2=ro[2],x2=ro[3];
    float area=fmaxf((y2-y1)*(x2-x1),1e-6f);
    float lv=floorf(4.f+log2f(sqrtf(area)/224.f));
    lv=fminf(fmaxf(lv,2.f),6.f);
    int li=(int)lv-2;
    int H=cH[li],W=cW[li];
    float Hf=(float)H,Wf=(float)W;
    float stride=cStrideF[li];
    const __nv_bfloat16* base=g.featsbf+((size_t)cHOff[li]+(size_t)b*H*W)*256;
    __nv_bfloat16* outp=&g.roifeatb[(size_t)br*12544];
    for(int p=0;p<49;p++){
        int py=p/7,px=p%7;
        float uy=((float)py+0.5f)/7.f, ux=((float)px+0.5f)/7.f;
        float ys=(y1+(y2-y1)*uy)/stride-0.5f;
        float xs=(x1+(x2-x1)*ux)/stride-0.5f;
        ys=fminf(fmaxf(ys,0.f),Hf-1.f);
        xs=fminf(fmaxf(xs,0.f),Wf-1.f);
        float y0=floorf(ys),x0=floorf(xs);
        float wy=ys-y0,wx=xs-x0;
        int y0i=(int)y0,x0i=(int)x0;
        int y1i=min(y0i+1,H-1),x1i=min(x0i+1,W-1);
        float2 p00=__bfloat1622float2(*(const __nv_bfloat162*)(base+((size_t)y0i*W+x0i)*256+c2*2));
        float2 p01=__bfloat1622float2(*(const __nv_bfloat162*)(base+((size_t)y0i*W+x1i)*256+c2*2));
        float2 p10=__bfloat1622float2(*(const __nv_bfloat162*)(base+((size_t)y1i*W+x0i)*256+c2*2));
        float2 p11=__bfloat1622float2(*(const __nv_bfloat162*)(base+((size_t)y1i*W+x1i)*256+c2*2));
        float w00=(1.f-wy)*(1.f-wx), w01=(1.f-wy)*wx;
        float w10=wy*(1.f-wx), w11=wy*wx;
        float vx=p00.x*w00+p01.x*w01+p10.x*w10+p11.x*w11;
        float vy=p00.y*w00+p01.y*w01+p10.y*w10+p11.y*w11;
        *(__nv_bfloat162*)(outp+p*256+c2*2)=__floats2bfloat162_rn(vx,vy);
    }
}

__global__ void softmax91(){
    int i=blockIdx.x*blockDim.x+threadIdx.x;
    if(i>=2000) return;
    float* p=&g.clsl[(size_t)i*91];
    float mx=p[0];
    for(int c=1;c<91;c++) mx=fmaxf(mx,p[c]);
    float sm=0.f;
    float e[91];
    for(int c=0;c<91;c++){ e[c]=expf(p[c]-mx); sm+=e[c]; }
    for(int c=0;c<91;c++) p[c]=e[c]/sm;
}

__device__ void nms_run(float* y1,float* x1,float* y2,float* x2,float* s,
                        int n,int iters,float th,float* ob,float* os){
    __shared__ float rv[256];
    __shared__ int ri[256];
    __shared__ float cb[4];
    int tid=threadIdx.x;
    for(int it=0;it<iters;it++){
        float bv=-3.0e38f; int bi=1<<30;
        for(int i=tid;i<n;i+=256){
            float v=s[i];
            if(v>bv||(v==bv&&i<bi)){ bv=v; bi=i; }
        }
        rv[tid]=bv; ri[tid]=bi; __syncthreads();
        for(int o=128;o>0;o>>=1){
            if(tid<o){
                float v=rv[tid+o]; int j=ri[tid+o];
                if(v>rv[tid]||(v==rv[tid]&&j<ri[tid])){ rv[tid]=v; ri[tid]=j; }
            }
            __syncthreads();
        }
        int j=ri[0]; float js=rv[0];
        if(js<=NEGF*0.5f){
            for(int r=it+tid;r<iters;r+=256){
                os[r]=NEGF;
                ob[r*4+0]=0.f; ob[r*4+1]=0.f; ob[r*4+2]=0.f; ob[r*4+3]=0.f;
            }
            __syncthreads();
            return;
        }
        if(tid==0){ cb[0]=y1[j]; cb[1]=x1[j]; cb[2]=y2[j]; cb[3]=x2[j]; }
        __syncthreads();
        float a1=cb[0],a2=cb[1],a3=cb[2],a4=cb[3];
        float aA=(a3-a1)*(a4-a2);
        for(int i=tid;i<n;i+=256){
            float yy1=fmaxf(a1,y1[i]), xx1=fmaxf(a2,x1[i]);
            float yy2=fminf(a3,y2[i]), xx2=fminf(a4,x2[i]);
            float inter=fmaxf(yy2-yy1,0.f)*fmaxf(xx2-xx1,0.f);
            float bA=(y2[i]-y1[i])*(x2[i]-x1[i]);
            float iou=inter/(aA+bA-inter+1e-8f);
            if(iou>=th) s[i]=NEGF;
        }
        __syncthreads();
        if(tid==0){
            s[j]=NEGF;
            os[it]=js;
            ob[it*4+0]=a1; ob[it*4+1]=a2; ob[it*4+2]=a3; ob[it*4+3]=a4;
        }
        __syncthreads();
    }
}

__global__ void nms_det(const float* __restrict__ iminfo){
    __shared__ float y1[1000],x1[1000],y2[1000],x2[1000],s[1000];
    int blk=blockIdx.x; int b=blk/90; int c=blk%90+1;
    int tid=threadIdx.x;
    float hI=iminfo[b*5+0], wI=iminfo[b*5+1];
    for(int i=tid;i<1000;i+=256){
        const float* ro=&g.rois[b][i*4];
        float ya1=ro[0],xa1=ro[1],ya2=ro[2],xa2=ro[3];
        float ha=ya2-ya1, wa=xa2-xa1;
        float yc=ya1+0.5f*ha, xc=xa1+0.5f*wa;
        const float* d=&g.boxl[((size_t)(b*1000+i)*91+c)*4];
        float dy=d[0]/10.f, dx=d[1]/10.f;
        float dh=fminf(d[2]/5.f,CLIPV), dw=fminf(d[3]/5.f,CLIPV);
        float pcy=dy*ha+yc, pcx=dx*wa+xc;
        float ph=expf(dh)*ha, pw=expf(dw)*wa;
        y1[i]=fminf(fmaxf(pcy-0.5f*ph,0.f),hI);
        x1[i]=fminf(fmaxf(pcx-0.5f*pw,0.f),wI);
        y2[i]=fminf(fmaxf(pcy+0.5f*ph,0.f),hI);
        x2[i]=fminf(fmaxf(pcx+0.5f*pw,0.f),wI);
        float p=g.clsl[(size_t)(b*1000+i)*91+c];
        s[i]=(p>=0.05f)?p:NEGF;
    }
    __syncthreads();
    nms_run(y1,x1,y2,x2,s,1000,100,0.5f,&g.dnb[b][(c-1)*400],&g.dns[b][(c-1)*100]);
}

__global__ void zero_out(float* out,int out_size){
    int i=blockIdx.x*256+threadIdx.x;
    if(i<out_size) out[i]=0.f;
}

__global__ void det_rank(float* out,int out_size){
    extern __shared__ unsigned long long dk[];
    int b=blockIdx.x;
    int chunk=blockIdx.y;
    int tid=threadIdx.x;
    for(int i=tid;i<9000;i+=1024)
        dk[i]=(((unsigned long long)skey(g.dns[b][i]))<<32)|(unsigned)(~(unsigned)i);
    __syncthreads();
    int i0=chunk*1125, i1=i0+1125;
    for(int i=i0+tid;i<i1;i+=1024){
        unsigned long long me=dk[i];
        int rank=0;
        for(int j=0;j<9000;j++) rank+=(dk[j]>me);
        if(rank<100){
            float sc=g.dns[b][i];
            bool valid=sc>0.f;
            if(valid){
                int ob=2+b*400+rank*4;
                for(int d=0;d<4;d++){
                    int o=ob+d;
                    if(o<out_size) out[o]=g.dnb[b][i*4+d];
                }
                int oc=2+800+b*100+rank;
                if(oc<out_size) out[oc]=(float)(i/100+1);
                int os=2+1000+b*100+rank;
                if(os<out_size) out[os]=sc;
                if(b<out_size) atomicAdd(&out[b],1.f);
            }
        }
    }
}

extern "C" void kernel_launch(void* const* d_in,const int* in_sizes,int n_in,
                              void* d_out,int out_size){
    const float* feats[5];
    for(int i=0;i<5;i++) feats[i]=(const float*)d_in[i];
    const float* iminfo=(const float*)d_in[5];
    const float* cw =(const float*)d_in[6];
    const float* cbv=(const float*)d_in[7];
    const float* sw =(const float*)d_in[8];
    const float* sb =(const float*)d_in[9];
    const float* bw =(const float*)d_in[10];
    const float* bbv=(const float*)d_in[11];
    const float* fc1w=(const float*)d_in[12];
    const float* fc1b=(const float*)d_in[13];
    const float* fc2w=(const float*)d_in[14];
    const float* fc2b=(const float*)d_in[15];
    const float* clsw=(const float*)d_in[16];
    const float* clsb=(const float*)d_in[17];
    const float* boxw=(const float*)d_in[18];
    const float* boxb=(const float*)d_in[19];

    Scratch* gp=nullptr;
    cudaGetSymbolAddress((void**)&gp,g);

    static int attr_done=0;
    if(!attr_done){
        cudaFuncSetAttribute(nms_lvl_v2,cudaFuncAttributeMaxDynamicSharedMemorySize,152*1024);
        cudaFuncSetAttribute(det_rank,cudaFuncAttributeMaxDynamicSharedMemorySize,80*1024);
        attr_done=1;
    }
    const int NMS_SMEM=5120*4+32000*4+32*4+16;
    const int DET_SMEM=9000*8;

    init_kernel<<<1,32>>>();
    cvt_feats<<<dim3(17472,5),256>>>(feats[0],feats[1],feats[2],feats[3],feats[4]);
    twcvt<<<dim3(72,8),dim3(32,8)>>>(cw,gp->cwT,2304,256,256);
    gemm_bf16<2,true,true><<<dim3(2,1455),256>>>(gp->featsbf,gp->cwT,cbv,gp->hb,186186,256,2304);
    rpn_head_scores<<<dim3(546,5),256>>>(sw,sb);
    select_topk_all<<<10,1024>>>();
    bitonic_lvl<<<10,1024>>>();
    rpn_decode_all<<<10,1024>>>(iminfo,bw,bbv);
    nms_lvl_v2<<<10,1024,NMS_SMEM>>>();
    cat_rank<<<2,1024>>>();

    roialign<<<2000,128>>>();

    twcvt<<<dim3(392,32),dim3(32,8)>>>(fc1w,gp->fc1wT,12544,1024,1024);
    twcvt<<<dim3(32,32),dim3(32,8)>>>(fc2w,gp->fc2wT,1024,1024,1024);
    twcvt<<<dim3(32,4),dim3(32,8)>>>(clsw,gp->clswT,1024,91,128);
    twcvt<<<dim3(32,12),dim3(32,8)>>>(boxw,gp->boxwT,1024,364,384);
    padbias<<<1,512>>>(clsb,boxb);

    gemm_bf16<0,true,true ><<<dim3(8,16),256>>>(gp->roifeatb,gp->fc1wT,fc1b,gp->h1b,2000,1024,12544);
    gemm_bf16<0,true,true ><<<dim3(8,16),256>>>(gp->h1b,gp->fc2wT,fc2b,gp->h2b,2000,1024,1024);
    gemm_bf16<0,false,false><<<dim3(1,16),256>>>(gp->h2b,gp->clswT,gp->clsbPad,gp->clsl,2000,91,1024);
    gemm_bf16<0,false,false><<<dim3(3,16),256>>>(gp->h2b,gp->boxwT,gp->boxbPad,gp->boxl,2000,364,1024);

    softmax91<<<8,256>>>();
    nms_det<<<180,256>>>(iminfo);
    zero_out<<<(out_size+255)/256,256>>>((float*)d_out,out_size);
    det_rank<<<dim3(2,8),1024,DET_SMEM>>>((float*)d_out,out_size);
}